// round 7
// baseline (speedup 1.0000x reference)
#include <cuda_runtime.h>
#include <cstdint>

typedef unsigned long long ull;

#define PX 68    // Xst pitch (floats)
#define PQ 132   // Q/K/V/Y pitch
#define PS 35    // combine-scratch pitch (stride 3 banks -> conflict-free)
#define SC_Q 0.17677669529663687f  // 32^-0.5

// packed fp32x2 FMA (sm_10x): doubles fp32 throughput vs FFMA
__device__ __forceinline__ void fma2(ull &d, ull a, ull b) {
    asm volatile("fma.rn.f32x2 %0, %1, %2, %0;" : "+l"(d) : "l"(a), "l"(b));
}
__device__ __forceinline__ ull pack2(float x) {
    ull d; unsigned u = __float_as_uint(x);
    asm volatile("mov.b64 %0, {%1, %1};" : "=l"(d) : "r"(u));
    return d;
}
__device__ __forceinline__ float2 unpack2(ull d) {
    float2 r;
    asm volatile("mov.b64 {%0, %1}, %2;" : "=f"(r.x), "=f"(r.y) : "l"(d));
    return r;
}

// Pre-transposed weights: Wt[k][j], j in [0,384) = qkv row j, j in [384,512) = proj row j-384
__device__ float Wt_g[128 * 512];

__global__ void __launch_bounds__(256)
prep_w_kernel(const float* __restrict__ qkv_w, const float* __restrict__ proj_w) {
    int i = blockIdx.x * 256 + threadIdx.x;   // 65536 total
    int k = i >> 9, j = i & 511;
    Wt_g[i] = (j < 384) ? qkv_w[j * 128 + k] : proj_w[(j - 384) * 128 + k];
}

// smem (floats): Xst[128*PX] | Qs/Ks/Vs[64*PQ each] | Bt[900] | Sc[256*PS]  (~176 KB)
#define SMEM_FLOATS (128*PX + 3*64*PQ + 900 + 256*PS)

__global__ void __launch_bounds__(512, 1)
wattn_kernel(const float* __restrict__ x, const float* __restrict__ qkv_b,
             const float* __restrict__ proj_b, const float* __restrict__ rpb,
             float* __restrict__ out)
{
    extern __shared__ float sm[];
    float* Xst = sm;                  // [128][PX] input (k-major), later attn out (k-major)
    float* Qs  = Xst + 128 * PX;      // [64][PQ] Q (prescaled), later final Y
    float* Ks  = Qs + 64 * PQ;
    float* Vs  = Ks + 64 * PQ;
    float* Bt  = Vs + 64 * PQ;        // rpb [225*4]
    float* Sc  = Bt + 900;            // [256][PS] flash-combine scratch

    const int tid = threadIdx.x;
    int wid = blockIdx.x;
    const int wn = wid & 7;  wid >>= 3;
    const int hn = wid & 7;  wid >>= 3;
    const int v  = wid % 5;  wid /= 5;
    const int u  = wid % 5;
    const int b  = wid / 5;

    // base for (b, c=0, u, v): layout (B,C,U,V,H,W), C-stride = 25*4096 = 102400
    const int base = (((b << 7) * 5 + u) * 5 + v) * 4096;
    const float* xb = x + base;

    // ---- Phase 1: roll + window gather into Xst[c][s]; rpb -> Bt ----
    #pragma unroll
    for (int i = tid; i < 8192; i += 512) {
        int c = i >> 6, s = i & 63;
        int sh = ((hn << 3) + (s >> 3) - 4) & 63;
        int sw = ((wn << 3) + (s & 7) - 4) & 63;
        Xst[c * PX + s] = __ldg(xb + c * 102400 + sh * 64 + sw);
    }
    for (int i = tid; i < 900; i += 512) Bt[i] = rpb[i];
    __syncthreads();

    const int rt = tid >> 6;   // row block: rows rt*8..+7 (warp-uniform -> A broadcast)
    const int ct = tid & 63;   // col pair: j = sec*128 + ct*2

    // ---- Phase 2: FUSED QKV GEMM. 512 threads, 8 rows x (3 x 2 cols). ----
    {
        ull acc[3][8];
        #pragma unroll
        for (int p = 0; p < 3; p++)
            #pragma unroll
            for (int r = 0; r < 8; r++) acc[p][r] = 0ULL;

        const float* Bp = Wt_g + (ct << 1);
        #pragma unroll 4
        for (int k = 0; k < 128; k++) {
            const float* Ar = Xst + k * PX + (rt << 3);
            float4 a0 = *(const float4*)(Ar);
            float4 a1 = *(const float4*)(Ar + 4);
            const float* Bk = Bp + (k << 9);
            ull b0 = *(const ull*)(Bk);
            ull b1 = *(const ull*)(Bk + 128);
            ull b2 = *(const ull*)(Bk + 256);
            float ar[8] = {a0.x, a0.y, a0.z, a0.w, a1.x, a1.y, a1.z, a1.w};
            #pragma unroll
            for (int r = 0; r < 8; r++) {
                ull ap = pack2(ar[r]);
                fma2(acc[0][r], ap, b0);
                fma2(acc[1][r], ap, b1);
                fma2(acc[2][r], ap, b2);
            }
        }

        // epilogue x3: remap interleaved-head channels to Q/K/V
        #pragma unroll
        for (int p = 0; p < 3; p++) {
            int j  = (p << 7) + (ct << 1);
            int hh = j / 96;
            int r  = j - hh * 96;
            int seg = r >> 5;
            int col = (hh << 5) + (r & 31);
            float* dst = (seg == 0) ? Qs : (seg == 1) ? Ks : Vs;
            float sc   = (seg == 0) ? SC_Q : 1.0f;
            float2 bb = *(const float2*)(qkv_b + j);
            #pragma unroll
            for (int r8 = 0; r8 < 8; r8++) {
                int s = (rt << 3) + r8;
                float2 pv = unpack2(acc[p][r8]);
                float2 o;
                o.x = (pv.x + bb.x) * sc;
                o.y = (pv.y + bb.y) * sc;
                *(float2*)(dst + s * PQ + col) = o;
            }
        }
    }
    __syncthreads();

    // ---- Phase 3: attention, t-split flash-combine. thread = (g, h, q), 32 keys each. ----
    {
        const int g = tid >> 8;          // key-half
        const int h = (tid >> 6) & 3;
        const int q = tid & 63;
        const int hq = tid & 255;

        ulonglong2 qp[8];
        const ulonglong2* qr = (const ulonglong2*)(Qs + q * PQ + (h << 5));
        #pragma unroll
        for (int d = 0; d < 8; d++) qp[d] = qr[d];

        float lg[32];
        const int qi = q >> 3, qj = q & 7;
        const int t0 = g << 5;
        #pragma unroll
        for (int tt = 0; tt < 32; tt++) {
            int t = t0 + tt;
            const ulonglong2* kr = (const ulonglong2*)(Ks + t * PQ + (h << 5));
            ull a0 = 0ULL, a1 = 0ULL, a2 = 0ULL, a3 = 0ULL;
            #pragma unroll
            for (int d = 0; d < 8; d += 2) {
                ulonglong2 k0 = kr[d];
                ulonglong2 k1 = kr[d + 1];
                fma2(a0, qp[d].x, k0.x);
                fma2(a1, qp[d].y, k0.y);
                fma2(a2, qp[d + 1].x, k1.x);
                fma2(a3, qp[d + 1].y, k1.y);
            }
            float2 s0 = unpack2(a0), s1 = unpack2(a1), s2 = unpack2(a2), s3 = unpack2(a3);
            int ridx = (qi - (t >> 3) + 7) * 15 + (qj - (t & 7) + 7);
            lg[tt] = ((s0.x + s0.y) + (s1.x + s1.y)) + ((s2.x + s2.y) + (s3.x + s3.y))
                     + Bt[ridx * 4 + h];
        }
        float m = lg[0];
        #pragma unroll
        for (int tt = 1; tt < 32; tt++) m = fmaxf(m, lg[tt]);
        float l = 0.f;
        #pragma unroll
        for (int tt = 0; tt < 32; tt++) { float e = __expf(lg[tt] - m); lg[tt] = e; l += e; }

        ull op[16];
        #pragma unroll
        for (int d = 0; d < 16; d++) op[d] = 0ULL;
        #pragma unroll
        for (int tt = 0; tt < 32; tt++) {
            ull pp = pack2(lg[tt]);
            const ulonglong2* vr = (const ulonglong2*)(Vs + (t0 + tt) * PQ + (h << 5));
            #pragma unroll
            for (int d = 0; d < 8; d++) {
                fma2(op[2 * d],     pp, vr[d].x);
                fma2(op[2 * d + 1], pp, vr[d].y);
            }
        }

        float* myS = Sc + hq * PS;
        if (g == 1) {
            #pragma unroll
            for (int d = 0; d < 16; d++) {
                float2 o2 = unpack2(op[d]);
                myS[2 * d]     = o2.x;
                myS[2 * d + 1] = o2.y;
            }
            myS[32] = m;
            myS[33] = l;
        }
        __syncthreads();
        if (g == 0) {
            float m1 = myS[32], l1 = myS[33];
            float M  = fmaxf(m, m1);
            float s0 = __expf(m - M);
            float s1 = __expf(m1 - M);
            float inv = __fdividef(1.0f, l * s0 + l1 * s1);
            // write combined attention output transposed (k-major) into Xst
            #pragma unroll
            for (int d = 0; d < 16; d++) {
                float2 o2 = unpack2(op[d]);
                int c = (h << 5) + 2 * d;
                Xst[c * PX + q]       = (o2.x * s0 + myS[2 * d]     * s1) * inv;
                Xst[(c + 1) * PX + q] = (o2.y * s0 + myS[2 * d + 1] * s1) * inv;
            }
        }
    }
    __syncthreads();

    // ---- Phase 4: proj GEMM. 512 threads, 8 rows x 2 cols, full k. -> Y into Qs ----
    {
        ull pacc[8];
        #pragma unroll
        for (int r = 0; r < 8; r++) pacc[r] = 0ULL;

        const float* Bq = Wt_g + 384 + (ct << 1);
        #pragma unroll 4
        for (int k = 0; k < 128; k++) {
            const float* Ar = Xst + k * PX + (rt << 3);
            float4 a0 = *(const float4*)(Ar);
            float4 a1 = *(const float4*)(Ar + 4);
            ull bb = *(const ull*)(Bq + (k << 9));
            float ar[8] = {a0.x, a0.y, a0.z, a0.w, a1.x, a1.y, a1.z, a1.w};
            #pragma unroll
            for (int r = 0; r < 8; r++) fma2(pacc[r], pack2(ar[r]), bb);
        }

        int j = ct << 1;
        float2 bb = *(const float2*)(proj_b + j);
        #pragma unroll
        for (int r8 = 0; r8 < 8; r8++) {
            int s = (rt << 3) + r8;
            float2 pv = unpack2(pacc[r8]);
            float2 o;
            o.x = pv.x + bb.x;
            o.y = pv.y + bb.y;
            *(float2*)(Qs + s * PQ + j) = o;
        }
    }
    __syncthreads();

    // ---- Phase 5: coalesced reverse-roll scatter ----
    float* ob = out + base;
    #pragma unroll
    for (int i = tid; i < 8192; i += 512) {
        int c = i >> 6, s = i & 63;
        int sh = ((hn << 3) + (s >> 3) - 4) & 63;
        int sw = ((wn << 3) + (s & 7) - 4) & 63;
        ob[c * 102400 + sh * 64 + sw] = Qs[s * PQ + c];
    }
}

extern "C" void kernel_launch(void* const* d_in, const int* in_sizes, int n_in,
                              void* d_out, int out_size) {
    (void)in_sizes; (void)n_in; (void)out_size;
    prep_w_kernel<<<256, 256>>>((const float*)d_in[1], (const float*)d_in[3]);
    size_t smem = SMEM_FLOATS * sizeof(float);
    cudaFuncSetAttribute(wattn_kernel, cudaFuncAttributeMaxDynamicSharedMemorySize, (int)smem);
    wattn_kernel<<<3200, 512, smem>>>(
        (const float*)d_in[0], (const float*)d_in[2], (const float*)d_in[4],
        (const float*)d_in[5], (float*)d_out);
}

// round 8
// speedup vs baseline: 1.0024x; 1.0024x over previous
#include <cuda_runtime.h>
#include <cstdint>

typedef unsigned long long ull;

#define PX 68    // Xst pitch (floats)
#define PQ 132   // Q/K/V/Y pitch
#define PS 35    // combine-scratch pitch (stride 3 banks -> conflict-free)
#define SC_Q 0.17677669529663687f  // 32^-0.5

// packed fp32x2 FMA (sm_10x): doubles fp32 throughput vs FFMA
__device__ __forceinline__ void fma2(ull &d, ull a, ull b) {
    asm volatile("fma.rn.f32x2 %0, %1, %2, %0;" : "+l"(d) : "l"(a), "l"(b));
}
__device__ __forceinline__ ull pack2(float x) {
    ull d; unsigned u = __float_as_uint(x);
    asm volatile("mov.b64 %0, {%1, %1};" : "=l"(d) : "r"(u));
    return d;
}
__device__ __forceinline__ float2 unpack2(ull d) {
    float2 r;
    asm volatile("mov.b64 {%0, %1}, %2;" : "=f"(r.x), "=f"(r.y) : "l"(d));
    return r;
}

// Pre-transposed weights: Wt[k][j], j in [0,384) = qkv row j, j in [384,512) = proj row j-384
__device__ float Wt_g[128 * 512];

__global__ void __launch_bounds__(256)
prep_w_kernel(const float* __restrict__ qkv_w, const float* __restrict__ proj_w) {
    int i = blockIdx.x * 256 + threadIdx.x;   // 65536 total
    int k = i >> 9, j = i & 511;
    Wt_g[i] = (j < 384) ? qkv_w[j * 128 + k] : proj_w[(j - 384) * 128 + k];
}

// smem (floats): Xst[128*PX] | Qs/Ks/Vs[64*PQ each] | Bt[900] | Sc[256*PS]  (~176 KB)
#define SMEM_FLOATS (128*PX + 3*64*PQ + 900 + 256*PS)

__global__ void __launch_bounds__(512, 1)
wattn_kernel(const float* __restrict__ x, const float* __restrict__ qkv_b,
             const float* __restrict__ proj_b, const float* __restrict__ rpb,
             float* __restrict__ out)
{
    extern __shared__ float sm[];
    float* Xst = sm;                  // [128][PX] input (k-major), later attn out (k-major)
    float* Qs  = Xst + 128 * PX;      // [64][PQ] Q (prescaled), later final Y
    float* Ks  = Qs + 64 * PQ;
    float* Vs  = Ks + 64 * PQ;
    float* Bt  = Vs + 64 * PQ;        // rpb [225*4]
    float* Sc  = Bt + 900;            // [256][PS] flash-combine scratch

    const int tid = threadIdx.x;
    int wid = blockIdx.x;
    const int wn = wid & 7;  wid >>= 3;
    const int hn = wid & 7;  wid >>= 3;
    const int v  = wid % 5;  wid /= 5;
    const int u  = wid % 5;
    const int b  = wid / 5;

    // base for (b, c=0, u, v): layout (B,C,U,V,H,W), C-stride = 25*4096 = 102400
    const int base = (((b << 7) * 5 + u) * 5 + v) * 4096;
    const float* xb = x + base;

    // ---- Phase 1: roll + window gather into Xst[c][s]; rpb -> Bt ----
    #pragma unroll
    for (int i = tid; i < 8192; i += 512) {
        int c = i >> 6, s = i & 63;
        int sh = ((hn << 3) + (s >> 3) - 4) & 63;
        int sw = ((wn << 3) + (s & 7) - 4) & 63;
        Xst[c * PX + s] = __ldg(xb + c * 102400 + sh * 64 + sw);
    }
    for (int i = tid; i < 900; i += 512) Bt[i] = rpb[i];
    __syncthreads();

    const int rt = tid >> 6;   // row block: rows rt*8..+7 (warp-uniform -> A broadcast)
    const int ct = tid & 63;   // col pair: j = sec*128 + ct*2

    // ---- Phase 2: FUSED QKV GEMM. 512 threads, 8 rows x (3 x 2 cols). ----
    {
        ull acc[3][8];
        #pragma unroll
        for (int p = 0; p < 3; p++)
            #pragma unroll
            for (int r = 0; r < 8; r++) acc[p][r] = 0ULL;

        const float* Bp = Wt_g + (ct << 1);
        #pragma unroll 4
        for (int k = 0; k < 128; k++) {
            const float* Ar = Xst + k * PX + (rt << 3);
            float4 a0 = *(const float4*)(Ar);
            float4 a1 = *(const float4*)(Ar + 4);
            const float* Bk = Bp + (k << 9);
            ull b0 = *(const ull*)(Bk);
            ull b1 = *(const ull*)(Bk + 128);
            ull b2 = *(const ull*)(Bk + 256);
            float ar[8] = {a0.x, a0.y, a0.z, a0.w, a1.x, a1.y, a1.z, a1.w};
            #pragma unroll
            for (int r = 0; r < 8; r++) {
                ull ap = pack2(ar[r]);
                fma2(acc[0][r], ap, b0);
                fma2(acc[1][r], ap, b1);
                fma2(acc[2][r], ap, b2);
            }
        }

        // epilogue x3: remap interleaved-head channels to Q/K/V
        #pragma unroll
        for (int p = 0; p < 3; p++) {
            int j  = (p << 7) + (ct << 1);
            int hh = j / 96;
            int r  = j - hh * 96;
            int seg = r >> 5;
            int col = (hh << 5) + (r & 31);
            float* dst = (seg == 0) ? Qs : (seg == 1) ? Ks : Vs;
            float sc   = (seg == 0) ? SC_Q : 1.0f;
            float2 bb = *(const float2*)(qkv_b + j);
            #pragma unroll
            for (int r8 = 0; r8 < 8; r8++) {
                int s = (rt << 3) + r8;
                float2 pv = unpack2(acc[p][r8]);
                float2 o;
                o.x = (pv.x + bb.x) * sc;
                o.y = (pv.y + bb.y) * sc;
                *(float2*)(dst + s * PQ + col) = o;
            }
        }
    }
    __syncthreads();

    // ---- Phase 3: attention, t-split flash-combine. thread = (g, h, q), 32 keys each. ----
    {
        const int g = tid >> 8;          // key-half
        const int h = (tid >> 6) & 3;
        const int q = tid & 63;
        const int hq = tid & 255;

        ulonglong2 qp[8];
        const ulonglong2* qr = (const ulonglong2*)(Qs + q * PQ + (h << 5));
        #pragma unroll
        for (int d = 0; d < 8; d++) qp[d] = qr[d];

        float lg[32];
        const int qi = q >> 3, qj = q & 7;
        const int t0 = g << 5;
        #pragma unroll
        for (int tt = 0; tt < 32; tt++) {
            int t = t0 + tt;
            const ulonglong2* kr = (const ulonglong2*)(Ks + t * PQ + (h << 5));
            ull a0 = 0ULL, a1 = 0ULL, a2 = 0ULL, a3 = 0ULL;
            #pragma unroll
            for (int d = 0; d < 8; d += 2) {
                ulonglong2 k0 = kr[d];
                ulonglong2 k1 = kr[d + 1];
                fma2(a0, qp[d].x, k0.x);
                fma2(a1, qp[d].y, k0.y);
                fma2(a2, qp[d + 1].x, k1.x);
                fma2(a3, qp[d + 1].y, k1.y);
            }
            float2 s0 = unpack2(a0), s1 = unpack2(a1), s2 = unpack2(a2), s3 = unpack2(a3);
            int ridx = (qi - (t >> 3) + 7) * 15 + (qj - (t & 7) + 7);
            lg[tt] = ((s0.x + s0.y) + (s1.x + s1.y)) + ((s2.x + s2.y) + (s3.x + s3.y))
                     + Bt[ridx * 4 + h];
        }
        float m = lg[0];
        #pragma unroll
        for (int tt = 1; tt < 32; tt++) m = fmaxf(m, lg[tt]);
        float l = 0.f;
        #pragma unroll
        for (int tt = 0; tt < 32; tt++) { float e = __expf(lg[tt] - m); lg[tt] = e; l += e; }

        ull op[16];
        #pragma unroll
        for (int d = 0; d < 16; d++) op[d] = 0ULL;
        #pragma unroll
        for (int tt = 0; tt < 32; tt++) {
            ull pp = pack2(lg[tt]);
            const ulonglong2* vr = (const ulonglong2*)(Vs + (t0 + tt) * PQ + (h << 5));
            #pragma unroll
            for (int d = 0; d < 8; d++) {
                fma2(op[2 * d],     pp, vr[d].x);
                fma2(op[2 * d + 1], pp, vr[d].y);
            }
        }

        float* myS = Sc + hq * PS;
        if (g == 1) {
            #pragma unroll
            for (int d = 0; d < 16; d++) {
                float2 o2 = unpack2(op[d]);
                myS[2 * d]     = o2.x;
                myS[2 * d + 1] = o2.y;
            }
            myS[32] = m;
            myS[33] = l;
        }
        __syncthreads();
        if (g == 0) {
            float m1 = myS[32], l1 = myS[33];
            float M  = fmaxf(m, m1);
            float s0 = __expf(m - M);
            float s1 = __expf(m1 - M);
            float inv = __fdividef(1.0f, l * s0 + l1 * s1);
            // write combined attention output transposed (k-major) into Xst
            #pragma unroll
            for (int d = 0; d < 16; d++) {
                float2 o2 = unpack2(op[d]);
                int c = (h << 5) + 2 * d;
                Xst[c * PX + q]       = (o2.x * s0 + myS[2 * d]     * s1) * inv;
                Xst[(c + 1) * PX + q] = (o2.y * s0 + myS[2 * d + 1] * s1) * inv;
            }
        }
    }
    __syncthreads();

    // ---- Phase 4: proj GEMM. 512 threads, 8 rows x 2 cols, full k. -> Y into Qs ----
    {
        ull pacc[8];
        #pragma unroll
        for (int r = 0; r < 8; r++) pacc[r] = 0ULL;

        const float* Bq = Wt_g + 384 + (ct << 1);
        #pragma unroll 4
        for (int k = 0; k < 128; k++) {
            const float* Ar = Xst + k * PX + (rt << 3);
            float4 a0 = *(const float4*)(Ar);
            float4 a1 = *(const float4*)(Ar + 4);
            ull bb = *(const ull*)(Bq + (k << 9));
            float ar[8] = {a0.x, a0.y, a0.z, a0.w, a1.x, a1.y, a1.z, a1.w};
            #pragma unroll
            for (int r = 0; r < 8; r++) fma2(pacc[r], pack2(ar[r]), bb);
        }

        int j = ct << 1;
        float2 bb = *(const float2*)(proj_b + j);
        #pragma unroll
        for (int r8 = 0; r8 < 8; r8++) {
            int s = (rt << 3) + r8;
            float2 pv = unpack2(pacc[r8]);
            float2 o;
            o.x = pv.x + bb.x;
            o.y = pv.y + bb.y;
            *(float2*)(Qs + s * PQ + j) = o;
        }
    }
    __syncthreads();

    // ---- Phase 5: coalesced reverse-roll scatter ----
    float* ob = out + base;
    #pragma unroll
    for (int i = tid; i < 8192; i += 512) {
        int c = i >> 6, s = i & 63;
        int sh = ((hn << 3) + (s >> 3) - 4) & 63;
        int sw = ((wn << 3) + (s & 7) - 4) & 63;
        ob[c * 102400 + sh * 64 + sw] = Qs[s * PQ + c];
    }
}

extern "C" void kernel_launch(void* const* d_in, const int* in_sizes, int n_in,
                              void* d_out, int out_size) {
    (void)in_sizes; (void)n_in; (void)out_size;
    prep_w_kernel<<<256, 256>>>((const float*)d_in[1], (const float*)d_in[3]);
    size_t smem = SMEM_FLOATS * sizeof(float);
    cudaFuncSetAttribute(wattn_kernel, cudaFuncAttributeMaxDynamicSharedMemorySize, (int)smem);
    wattn_kernel<<<3200, 512, smem>>>(
        (const float*)d_in[0], (const float*)d_in[2], (const float*)d_in[4],
        (const float*)d_in[5], (float*)d_out);
}

// round 10
// speedup vs baseline: 1.4816x; 1.4781x over previous
#include <cuda_runtime.h>
#include <cuda_bf16.h>
#include <cstdint>

typedef unsigned long long ull;
#define SC_Q 0.17677669529663687f

// ---- smem byte offsets ----
#define OFF_XHI 0          // X/O hi bf16 [64][136] row-major (17408 B)
#define OFF_XLO 17408      // X/O lo
#define OFF_QS  34816      // f32 [64][132]
#define OFF_KS  68608
#define OFF_VS  102400
#define OFF_BT  136192     // rpb 900 f32
#define SMEM_BYTES 139808

#define PXB 272            // X row pitch bytes (136 bf16)
#define PQ  132            // Q/K/V/Y pitch floats

// fp32x2 packed helpers (attention)
__device__ __forceinline__ void fma2(ull &d, ull a, ull b) {
    asm volatile("fma.rn.f32x2 %0, %1, %2, %0;" : "+l"(d) : "l"(a), "l"(b));
}
__device__ __forceinline__ ull pack2(float x) {
    ull d; unsigned u = __float_as_uint(x);
    asm volatile("mov.b64 %0, {%1, %1};" : "=l"(d) : "r"(u));
    return d;
}
__device__ __forceinline__ float2 unpack2(ull d) {
    float2 r;
    asm volatile("mov.b64 {%0, %1}, %2;" : "=f"(r.x), "=f"(r.y) : "l"(d));
    return r;
}
__device__ __forceinline__ uint32_t smem_u32(const void* p) {
    uint32_t a;
    asm("{ .reg .u64 t; cvta.to.shared.u64 t, %1; cvt.u32.u64 %0, t; }" : "=r"(a) : "l"(p));
    return a;
}
// legacy tensor-core MMA (sm_80+, no arch-'a' feature needed)
__device__ __forceinline__ void mma16816(float (&d)[4], const uint32_t (&a)[4], const uint32_t (&b)[2]) {
    asm volatile(
        "mma.sync.aligned.m16n8k16.row.col.f32.bf16.bf16.f32 "
        "{%0,%1,%2,%3}, {%4,%5,%6,%7}, {%8,%9}, {%0,%1,%2,%3};"
        : "+f"(d[0]), "+f"(d[1]), "+f"(d[2]), "+f"(d[3])
        : "r"(a[0]), "r"(a[1]), "r"(a[2]), "r"(a[3]), "r"(b[0]), "r"(b[1]));
}
__device__ __forceinline__ void ldm4(uint32_t (&a)[4], uint32_t addr) {
    asm volatile("ldmatrix.sync.aligned.m8n8.x4.shared.b16 {%0,%1,%2,%3}, [%4];"
                 : "=r"(a[0]), "=r"(a[1]), "=r"(a[2]), "=r"(a[3]) : "r"(addr));
}

// pre-split weights: rows 0..383 = qkv_w rows (natural order), 384..511 = proj_w rows; [n][k=128]
__device__ __align__(16) __nv_bfloat16 Whi_g[512 * 128];
__device__ __align__(16) __nv_bfloat16 Wlo_g[512 * 128];

__global__ void __launch_bounds__(256)
prep_w_kernel(const float* __restrict__ qkv_w, const float* __restrict__ proj_w) {
    int i = blockIdx.x * 256 + threadIdx.x;     // 65536
    int n = i >> 7, k = i & 127;
    float v = (n < 384) ? qkv_w[n * 128 + k] : proj_w[(n - 384) * 128 + k];
    __nv_bfloat16 hi = __float2bfloat16(v);
    Whi_g[i] = hi;
    Wlo_g[i] = __float2bfloat16(v - __bfloat162float(hi));
}

__global__ void __launch_bounds__(256, 1)
wattn_kernel(const float* __restrict__ x, const float* __restrict__ qkv_b,
             const float* __restrict__ proj_b, const float* __restrict__ rpb,
             float* __restrict__ out)
{
    extern __shared__ char smc[];
    float* Qs = (float*)(smc + OFF_QS);
    float* Ks = (float*)(smc + OFF_KS);
    float* Vs = (float*)(smc + OFF_VS);
    float* Bt = (float*)(smc + OFF_BT);

    const int tid = threadIdx.x;
    const int wrp = tid >> 5, lane = tid & 31;
    const uint32_t smb = smem_u32(smc);

    int wid = blockIdx.x;
    const int wn = wid & 7;  wid >>= 3;
    const int hn = wid & 7;  wid >>= 3;
    const int v  = wid % 5;  wid /= 5;
    const int u  = wid % 5;
    const int b  = wid / 5;
    const int base = (((b << 7) * 5 + u) * 5 + v) * 4096;
    const float* xb = x + base;

    // ---- Phase 1: roll+gather X -> bf16 hi/lo row-major tiles; rpb -> Bt ----
    #pragma unroll
    for (int i = tid; i < 4096; i += 256) {
        int m = i & 63, cp = i >> 6;          // token m, channel pair cp
        int sh = ((hn << 3) + (m >> 3) - 4) & 63;
        int sw = ((wn << 3) + (m & 7) - 4) & 63;
        const float* px = xb + (cp << 1) * 102400 + sh * 64 + sw;
        float v0 = __ldg(px), v1 = __ldg(px + 102400);
        __nv_bfloat16 h0 = __float2bfloat16(v0), h1 = __float2bfloat16(v1);
        __nv_bfloat162 hp; hp.x = h0; hp.y = h1;
        __nv_bfloat162 lp;
        lp.x = __float2bfloat16(v0 - __bfloat162float(h0));
        lp.y = __float2bfloat16(v1 - __bfloat162float(h1));
        *(__nv_bfloat162*)(smc + OFF_XHI + m * PXB + cp * 4) = hp;
        *(__nv_bfloat162*)(smc + OFF_XLO + m * PXB + cp * 4) = lp;
    }
    for (int i = tid; i < 900; i += 256) Bt[i] = rpb[i];
    __syncthreads();

    // ldmatrix lane address (row-major A, m16k16 frag via x4)
    const uint32_t aAddr = smb + ((((lane >> 3) & 1) * 8 + (lane & 7)) * PXB) + (((lane >> 4) & 1) * 16);
    const int bn = lane >> 2;          // B frag: n offset within 8-col tile
    const int bk = (lane & 3) * 2;     // B frag: k offset within 16-k step

    // ---- Phase 2: QKV MMA. warp w -> n-cols [w*48, w*48+48) ----
    {
        const int n0 = wrp * 48;
        float D[6][4][4];
        #pragma unroll
        for (int j = 0; j < 6; j++)
            #pragma unroll
            for (int mt = 0; mt < 4; mt++)
                #pragma unroll
                for (int e = 0; e < 4; e++) D[j][mt][e] = 0.f;

        #pragma unroll 1
        for (int s = 0; s < 8; s++) {
            uint32_t Ah[4][4], Al[4][4];
            #pragma unroll
            for (int mt = 0; mt < 4; mt++) {
                ldm4(Ah[mt], aAddr + OFF_XHI + mt * 16 * PXB + s * 32);
                ldm4(Al[mt], aAddr + OFF_XLO + mt * 16 * PXB + s * 32);
            }
            #pragma unroll
            for (int j = 0; j < 6; j++) {
                int n = n0 + j * 8 + bn;
                int kb = s * 16 + bk;
                const __nv_bfloat16* wh = Whi_g + n * 128 + kb;
                const __nv_bfloat16* wl = Wlo_g + n * 128 + kb;
                uint32_t bh[2], bl[2];
                bh[0] = *(const uint32_t*)(wh);
                bh[1] = *(const uint32_t*)(wh + 8);
                bl[0] = *(const uint32_t*)(wl);
                bl[1] = *(const uint32_t*)(wl + 8);
                #pragma unroll
                for (int mt = 0; mt < 4; mt++) {
                    mma16816(D[j][mt], Ah[mt], bh);
                    mma16816(D[j][mt], Al[mt], bh);
                    mma16816(D[j][mt], Ah[mt], bl);
                }
            }
        }
        // epilogue: head-deinterleave remap + bias (+SC_Q on q)
        #pragma unroll
        for (int j = 0; j < 6; j++) {
            int c  = n0 + j * 8 + (lane & 3) * 2;
            int hh = c / 96, r = c - hh * 96;
            int seg = r >> 5, col = (hh << 5) + (r & 31);
            float* dst = (seg == 0) ? Qs : (seg == 1) ? Ks : Vs;
            float sc   = (seg == 0) ? SC_Q : 1.0f;
            float2 bb = *(const float2*)(qkv_b + c);
            #pragma unroll
            for (int mt = 0; mt < 4; mt++) {
                int row = mt * 16 + (lane >> 2);
                float2 o0, o1;
                o0.x = (D[j][mt][0] + bb.x) * sc;
                o0.y = (D[j][mt][1] + bb.y) * sc;
                o1.x = (D[j][mt][2] + bb.x) * sc;
                o1.y = (D[j][mt][3] + bb.y) * sc;
                *(float2*)(dst + row * PQ + col)       = o0;
                *(float2*)(dst + (row + 8) * PQ + col) = o1;
            }
        }
    }
    __syncthreads();

    // ---- Phase 3: attention (R6-verified fp32). thread = (head h, query q). ----
    {
        const int h = tid >> 6;
        const int q = tid & 63;
        ulonglong2 qp[8];
        const ulonglong2* qr = (const ulonglong2*)(Qs + q * PQ + (h << 5));
        #pragma unroll
        for (int d = 0; d < 8; d++) qp[d] = qr[d];

        float lg[64];
        const int qi = q >> 3, qj = q & 7;
        #pragma unroll
        for (int t = 0; t < 64; t++) {
            const ulonglong2* kr = (const ulonglong2*)(Ks + t * PQ + (h << 5));
            ull a0 = 0ULL, a1 = 0ULL, a2 = 0ULL, a3 = 0ULL;
            #pragma unroll
            for (int d = 0; d < 8; d += 2) {
                ulonglong2 k0 = kr[d];
                ulonglong2 k1 = kr[d + 1];
                fma2(a0, qp[d].x, k0.x);
                fma2(a1, qp[d].y, k0.y);
                fma2(a2, qp[d + 1].x, k1.x);
                fma2(a3, qp[d + 1].y, k1.y);
            }
            float2 s0 = unpack2(a0), s1 = unpack2(a1), s2 = unpack2(a2), s3 = unpack2(a3);
            int ridx = (qi - (t >> 3) + 7) * 15 + (qj - (t & 7) + 7);
            lg[t] = ((s0.x + s0.y) + (s1.x + s1.y)) + ((s2.x + s2.y) + (s3.x + s3.y))
                    + Bt[ridx * 4 + h];
        }
        float m = lg[0];
        #pragma unroll
        for (int t = 1; t < 64; t++) m = fmaxf(m, lg[t]);
        float l = 0.f;
        #pragma unroll
        for (int t = 0; t < 64; t++) { float e = __expf(lg[t] - m); lg[t] = e; l += e; }
        float inv = __fdividef(1.0f, l);

        ull op[16];
        #pragma unroll
        for (int d = 0; d < 16; d++) op[d] = 0ULL;
        #pragma unroll
        for (int t = 0; t < 64; t++) {
            ull pp = pack2(lg[t]);
            const ulonglong2* vr = (const ulonglong2*)(Vs + t * PQ + (h << 5));
            #pragma unroll
            for (int d = 0; d < 8; d++) {
                fma2(op[2 * d],     pp, vr[d].x);
                fma2(op[2 * d + 1], pp, vr[d].y);
            }
        }
        // write O as bf16 hi/lo row-major into X buffers (proj A operand)
        #pragma unroll
        for (int d = 0; d < 16; d++) {
            float2 o2 = unpack2(op[d]);
            float o0 = o2.x * inv, o1 = o2.y * inv;
            int c = (h << 5) + 2 * d;
            __nv_bfloat16 h0 = __float2bfloat16(o0), h1 = __float2bfloat16(o1);
            __nv_bfloat162 hp; hp.x = h0; hp.y = h1;
            __nv_bfloat162 lp;
            lp.x = __float2bfloat16(o0 - __bfloat162float(h0));
            lp.y = __float2bfloat16(o1 - __bfloat162float(h1));
            *(__nv_bfloat162*)(smc + OFF_XHI + q * PXB + c * 2) = hp;
            *(__nv_bfloat162*)(smc + OFF_XLO + q * PXB + c * 2) = lp;
        }
    }
    __syncthreads();

    // ---- Phase 4: proj MMA. warp w -> n-cols [w*16, w*16+16). Y -> Qs. ----
    {
        const int n0 = wrp * 16;
        float D[2][4][4];
        #pragma unroll
        for (int j = 0; j < 2; j++)
            #pragma unroll
            for (int mt = 0; mt < 4; mt++)
                #pragma unroll
                for (int e = 0; e < 4; e++) D[j][mt][e] = 0.f;

        #pragma unroll 1
        for (int s = 0; s < 8; s++) {
            uint32_t Ah[4][4], Al[4][4];
            #pragma unroll
            for (int mt = 0; mt < 4; mt++) {
                ldm4(Ah[mt], aAddr + OFF_XHI + mt * 16 * PXB + s * 32);
                ldm4(Al[mt], aAddr + OFF_XLO + mt * 16 * PXB + s * 32);
            }
            #pragma unroll
            for (int j = 0; j < 2; j++) {
                int n = 384 + n0 + j * 8 + bn;
                int kb = s * 16 + bk;
                const __nv_bfloat16* wh = Whi_g + n * 128 + kb;
                const __nv_bfloat16* wl = Wlo_g + n * 128 + kb;
                uint32_t bh[2], bl[2];
                bh[0] = *(const uint32_t*)(wh);
                bh[1] = *(const uint32_t*)(wh + 8);
                bl[0] = *(const uint32_t*)(wl);
                bl[1] = *(const uint32_t*)(wl + 8);
                #pragma unroll
                for (int mt = 0; mt < 4; mt++) {
                    mma16816(D[j][mt], Ah[mt], bh);
                    mma16816(D[j][mt], Al[mt], bh);
                    mma16816(D[j][mt], Ah[mt], bl);
                }
            }
        }
        #pragma unroll
        for (int j = 0; j < 2; j++) {
            int c = n0 + j * 8 + (lane & 3) * 2;
            float2 bb = *(const float2*)(proj_b + c);
            #pragma unroll
            for (int mt = 0; mt < 4; mt++) {
                int row = mt * 16 + (lane >> 2);
                float2 o0, o1;
                o0.x = D[j][mt][0] + bb.x;
                o0.y = D[j][mt][1] + bb.y;
                o1.x = D[j][mt][2] + bb.x;
                o1.y = D[j][mt][3] + bb.y;
                *(float2*)(Qs + row * PQ + c)       = o0;
                *(float2*)(Qs + (row + 8) * PQ + c) = o1;
            }
        }
    }
    __syncthreads();

    // ---- Phase 5: coalesced reverse-roll scatter ----
    float* ob = out + base;
    #pragma unroll
    for (int i = tid; i < 8192; i += 256) {
        int c = i >> 6, s = i & 63;
        int sh = ((hn << 3) + (s >> 3) - 4) & 63;
        int sw = ((wn << 3) + (s & 7) - 4) & 63;
        ob[c * 102400 + sh * 64 + sw] = Qs[s * PQ + c];
    }
}

extern "C" void kernel_launch(void* const* d_in, const int* in_sizes, int n_in,
                              void* d_out, int out_size) {
    (void)in_sizes; (void)n_in; (void)out_size;
    prep_w_kernel<<<256, 256>>>((const float*)d_in[1], (const float*)d_in[3]);
    cudaFuncSetAttribute(wattn_kernel, cudaFuncAttributeMaxDynamicSharedMemorySize, SMEM_BYTES);
    wattn_kernel<<<3200, 256, SMEM_BYTES>>>(
        (const float*)d_in[0], (const float*)d_in[2], (const float*)d_in[4],
        (const float*)d_in[5], (float*)d_out);
}

// round 11
// speedup vs baseline: 1.7273x; 1.1658x over previous
#include <cuda_runtime.h>
#include <cuda_bf16.h>
#include <cstdint>

typedef unsigned long long ull;
#define SC_Q 0.17677669529663687f

// ---- smem byte offsets ----
#define OFF_XHI 0          // X/O hi bf16 [64 rows][256B] swizzled (16384)
#define OFF_XLO 16384
#define OFF_QS  32768      // f32 [64][132]
#define OFF_KS  66560
#define OFF_VS  100352
#define OFF_OS  134144     // f32 [64][132] attention-O scratch
#define OFF_BT  167936     // rpb 900 f32
#define SMEM_BYTES 171536

#define PQ 132             // f32 buffer pitch (33 x 16B units -> conflict-free float4)

// fp32x2 packed helpers (attention)
__device__ __forceinline__ void fma2(ull &d, ull a, ull b) {
    asm volatile("fma.rn.f32x2 %0, %1, %2, %0;" : "+l"(d) : "l"(a), "l"(b));
}
__device__ __forceinline__ ull pack2(float x) {
    ull d; unsigned u = __float_as_uint(x);
    asm volatile("mov.b64 %0, {%1, %1};" : "=l"(d) : "r"(u));
    return d;
}
__device__ __forceinline__ float2 unpack2(ull d) {
    float2 r;
    asm volatile("mov.b64 {%0, %1}, %2;" : "=f"(r.x), "=f"(r.y) : "l"(d));
    return r;
}
__device__ __forceinline__ uint32_t smem_u32(const void* p) {
    uint32_t a;
    asm("{ .reg .u64 t; cvta.to.shared.u64 t, %1; cvt.u32.u64 %0, t; }" : "=r"(a) : "l"(p));
    return a;
}
// legacy tensor-core MMA (sm_80+ PTX, runs on sm_103 fallback tensor path)
__device__ __forceinline__ void mma16816(float (&d)[4], const uint32_t (&a)[4], uint32_t b0, uint32_t b1) {
    asm volatile(
        "mma.sync.aligned.m16n8k16.row.col.f32.bf16.bf16.f32 "
        "{%0,%1,%2,%3}, {%4,%5,%6,%7}, {%8,%9}, {%0,%1,%2,%3};"
        : "+f"(d[0]), "+f"(d[1]), "+f"(d[2]), "+f"(d[3])
        : "r"(a[0]), "r"(a[1]), "r"(a[2]), "r"(a[3]), "r"(b0), "r"(b1));
}
__device__ __forceinline__ void ldm4(uint32_t (&a)[4], uint32_t addr) {
    asm volatile("ldmatrix.sync.aligned.m8n8.x4.shared.b16 {%0,%1,%2,%3}, [%4];"
                 : "=r"(a[0]), "=r"(a[1]), "=r"(a[2]), "=r"(a[3]) : "r"(addr));
}
__device__ __forceinline__ uint32_t bf2u(__nv_bfloat162 h) {
    uint32_t u; memcpy(&u, &h, 4); return u;
}

// Packed B fragments: [n8 0..63][s 0..7][lane 0..31] = {bh0,bh1,bl0,bl1}
// n8<48: qkv rows n8*8.., n8>=48: proj rows (n8-48)*8..  (256 KB)
__device__ __align__(16) uint4 Bpk_g[64 * 8 * 32];

__global__ void __launch_bounds__(256)
prep_w_kernel(const float* __restrict__ qkv_w, const float* __restrict__ proj_w) {
    int i = blockIdx.x * 256 + threadIdx.x;      // 16384 entries
    int n8 = i >> 8, s = (i >> 5) & 7, lane = i & 31;
    int n = n8 * 8 + (lane >> 2);
    int kb = s * 16 + (lane & 3) * 2;
    const float* src = (n < 384) ? (qkv_w + n * 128) : (proj_w + (n - 384) * 128);
    float e0 = src[kb], e1 = src[kb + 1], e8 = src[kb + 8], e9 = src[kb + 9];
    __nv_bfloat162 h01, h89, l01, l89;
    h01.x = __float2bfloat16(e0); h01.y = __float2bfloat16(e1);
    h89.x = __float2bfloat16(e8); h89.y = __float2bfloat16(e9);
    l01.x = __float2bfloat16(e0 - __bfloat162float(h01.x));
    l01.y = __float2bfloat16(e1 - __bfloat162float(h01.y));
    l89.x = __float2bfloat16(e8 - __bfloat162float(h89.x));
    l89.y = __float2bfloat16(e9 - __bfloat162float(h89.y));
    uint4 o; o.x = bf2u(h01); o.y = bf2u(h89); o.z = bf2u(l01); o.w = bf2u(l89);
    Bpk_g[i] = o;
}

__global__ void __launch_bounds__(256, 1)
wattn_kernel(const float* __restrict__ x, const float* __restrict__ qkv_b,
             const float* __restrict__ proj_b, const float* __restrict__ rpb,
             float* __restrict__ out)
{
    extern __shared__ char smc[];
    float* Qs = (float*)(smc + OFF_QS);
    float* Ks = (float*)(smc + OFF_KS);
    float* Vs = (float*)(smc + OFF_VS);
    float* Os = (float*)(smc + OFF_OS);
    float* Bt = (float*)(smc + OFF_BT);

    const int tid = threadIdx.x;
    const int wrp = tid >> 5, lane = tid & 31;
    const uint32_t smb = smem_u32(smc);

    int wid = blockIdx.x;
    const int wn = wid & 7;  wid >>= 3;
    const int hn = wid & 7;  wid >>= 3;
    const int v  = wid % 5;  wid /= 5;
    const int u  = wid % 5;
    const int b  = wid / 5;
    const int base = (((b << 7) * 5 + u) * 5 + v) * 4096;
    const float* xb = x + base;

    // ---- Phase 1: roll+gather X -> swizzled bf16 hi/lo tiles (conflict-free STS) ----
    {
        const int ml = (lane >> 2) & 7, cl = lane & 3;
        const int gm = wrp * 8 + ml;                  // token row 0..63
        const int gsh = ((hn << 3) + (gm >> 3) - 4) & 63;
        const int gsw = ((wn << 3) + (gm & 7) - 4) & 63;
        const float* gp = xb + gsh * 64 + gsw;
        const uint32_t rowb = (uint32_t)gm * 256u + (uint32_t)cl * 4u;
        #pragma unroll
        for (int it = 0; it < 16; it++) {
            int cp = it * 4 + cl;
            float v0 = __ldg(gp + (2 * cp) * 102400);
            float v1 = __ldg(gp + (2 * cp + 1) * 102400);
            uint32_t ad = rowb + (uint32_t)((it ^ (gm & 15)) << 4);
            __nv_bfloat162 hp, lp;
            hp.x = __float2bfloat16(v0); hp.y = __float2bfloat16(v1);
            lp.x = __float2bfloat16(v0 - __bfloat162float(hp.x));
            lp.y = __float2bfloat16(v1 - __bfloat162float(hp.y));
            *(__nv_bfloat162*)(smc + OFF_XHI + ad) = hp;
            *(__nv_bfloat162*)(smc + OFF_XLO + ad) = lp;
        }
    }
    for (int i = tid; i < 900; i += 256) Bt[i] = rpb[i];
    __syncthreads();

    // ldmatrix lane geometry (swizzled pitch-256 tiles)
    const int rl  = ((lane >> 3) & 1) * 8 + (lane & 7);   // row within 16-row tile
    const int h16 = (lane >> 4) & 1;                       // 16B half of 32B k-chunk
    const uint32_t aHiB = smb + OFF_XHI + (uint32_t)rl * 256u;
    const uint32_t aLoB = smb + OFF_XLO + (uint32_t)rl * 256u;
    const int bn = lane >> 2;  // (kept for epilogue col math parity)

    // ---- Phase 2: QKV MMA. warp w -> n-cols [w*48, w*48+48) ----
    {
        const int n0 = wrp * 48;
        float D[6][4][4];
        #pragma unroll
        for (int j = 0; j < 6; j++)
            #pragma unroll
            for (int mt = 0; mt < 4; mt++)
                #pragma unroll
                for (int e = 0; e < 4; e++) D[j][mt][e] = 0.f;

        #pragma unroll 1
        for (int s = 0; s < 8; s++) {
            uint32_t uoff = (uint32_t)(((s * 2 + h16) ^ rl) << 4);
            uint32_t Ah[4][4], Al[4][4];
            #pragma unroll
            for (int mt = 0; mt < 4; mt++) {
                ldm4(Ah[mt], aHiB + mt * 4096 + uoff);
                ldm4(Al[mt], aLoB + mt * 4096 + uoff);
            }
            #pragma unroll
            for (int j = 0; j < 6; j++) {
                uint4 bb = __ldg(&Bpk_g[((wrp * 6 + j) * 8 + s) * 32 + lane]);
                #pragma unroll
                for (int mt = 0; mt < 4; mt++) {
                    mma16816(D[j][mt], Ah[mt], bb.x, bb.y);
                    mma16816(D[j][mt], Al[mt], bb.x, bb.y);
                    mma16816(D[j][mt], Ah[mt], bb.z, bb.w);
                }
            }
        }
        // epilogue: head-deinterleave remap + bias (+SC_Q on q)
        #pragma unroll
        for (int j = 0; j < 6; j++) {
            int c  = n0 + j * 8 + (lane & 3) * 2;
            int hh = c / 96, r = c - hh * 96;
            int seg = r >> 5, col = (hh << 5) + (r & 31);
            float* dst = (seg == 0) ? Qs : (seg == 1) ? Ks : Vs;
            float sc   = (seg == 0) ? SC_Q : 1.0f;
            float2 bb = *(const float2*)(qkv_b + c);
            #pragma unroll
            for (int mt = 0; mt < 4; mt++) {
                int row = mt * 16 + (lane >> 2);
                float2 o0, o1;
                o0.x = (D[j][mt][0] + bb.x) * sc;
                o0.y = (D[j][mt][1] + bb.y) * sc;
                o1.x = (D[j][mt][2] + bb.x) * sc;
                o1.y = (D[j][mt][3] + bb.y) * sc;
                *(float2*)(dst + row * PQ + col)       = o0;
                *(float2*)(dst + (row + 8) * PQ + col) = o1;
            }
        }
    }
    __syncthreads();

    // ---- Phase 3: attention (fp32, verified). thread = (head h, query q). ----
    {
        const int h = tid >> 6;
        const int q = tid & 63;
        ulonglong2 qp[8];
        const ulonglong2* qr = (const ulonglong2*)(Qs + q * PQ + (h << 5));
        #pragma unroll
        for (int d = 0; d < 8; d++) qp[d] = qr[d];

        float lg[64];
        const int qi = q >> 3, qj = q & 7;
        #pragma unroll
        for (int t = 0; t < 64; t++) {
            const ulonglong2* kr = (const ulonglong2*)(Ks + t * PQ + (h << 5));
            ull a0 = 0ULL, a1 = 0ULL, a2 = 0ULL, a3 = 0ULL;
            #pragma unroll
            for (int d = 0; d < 8; d += 2) {
                ulonglong2 k0 = kr[d];
                ulonglong2 k1 = kr[d + 1];
                fma2(a0, qp[d].x, k0.x);
                fma2(a1, qp[d].y, k0.y);
                fma2(a2, qp[d + 1].x, k1.x);
                fma2(a3, qp[d + 1].y, k1.y);
            }
            float2 s0 = unpack2(a0), s1 = unpack2(a1), s2 = unpack2(a2), s3 = unpack2(a3);
            int ridx = (qi - (t >> 3) + 7) * 15 + (qj - (t & 7) + 7);
            lg[t] = ((s0.x + s0.y) + (s1.x + s1.y)) + ((s2.x + s2.y) + (s3.x + s3.y))
                    + Bt[ridx * 4 + h];
        }
        float m = lg[0];
        #pragma unroll
        for (int t = 1; t < 64; t++) m = fmaxf(m, lg[t]);
        float l = 0.f;
        #pragma unroll
        for (int t = 0; t < 64; t++) { float e = __expf(lg[t] - m); lg[t] = e; l += e; }
        float inv = __fdividef(1.0f, l);

        ull op[16];
        #pragma unroll
        for (int d = 0; d < 16; d++) op[d] = 0ULL;
        #pragma unroll
        for (int t = 0; t < 64; t++) {
            ull pp = pack2(lg[t]);
            const ulonglong2* vr = (const ulonglong2*)(Vs + t * PQ + (h << 5));
            #pragma unroll
            for (int d = 0; d < 8; d++) {
                fma2(op[2 * d],     pp, vr[d].x);
                fma2(op[2 * d + 1], pp, vr[d].y);
            }
        }
        // O -> fp32 scratch, conflict-free float4 rows
        #pragma unroll
        for (int d2 = 0; d2 < 8; d2++) {
            float2 a = unpack2(op[2 * d2]);
            float2 b2 = unpack2(op[2 * d2 + 1]);
            float4 o = make_float4(a.x * inv, a.y * inv, b2.x * inv, b2.y * inv);
            *(float4*)(Os + q * PQ + (h << 5) + d2 * 4) = o;
        }
    }
    __syncthreads();

    // ---- Phase 3b: transpose O fp32 -> swizzled bf16 hi/lo tiles (conflict-free) ----
    {
        const int ml2 = lane & 7, cl2 = lane >> 3;   // lane = cl2*8 + ml2
        const int m = wrp * 8 + ml2;
        #pragma unroll
        for (int it = 0; it < 8; it++) {
            int cq = it * 4 + cl2;                   // float-quad index 0..31
            float4 f = *(const float4*)(Os + m * PQ + cq * 4);
            uint32_t ad = (uint32_t)m * 256u +
                          (uint32_t)((((cq >> 1) ^ (m & 15)) << 4) + ((cq & 1) << 3));
            __nv_bfloat162 h01, h23, l01, l23;
            h01.x = __float2bfloat16(f.x); h01.y = __float2bfloat16(f.y);
            h23.x = __float2bfloat16(f.z); h23.y = __float2bfloat16(f.w);
            l01.x = __float2bfloat16(f.x - __bfloat162float(h01.x));
            l01.y = __float2bfloat16(f.y - __bfloat162float(h01.y));
            l23.x = __float2bfloat16(f.z - __bfloat162float(h23.x));
            l23.y = __float2bfloat16(f.w - __bfloat162float(h23.y));
            uint2 hh; hh.x = bf2u(h01); hh.y = bf2u(h23);
            uint2 ll; ll.x = bf2u(l01); ll.y = bf2u(l23);
            *(uint2*)(smc + OFF_XHI + ad) = hh;
            *(uint2*)(smc + OFF_XLO + ad) = ll;
        }
    }
    __syncthreads();

    // ---- Phase 4: proj MMA. warp w -> n-cols [w*16, w*16+16). Y -> Qs. ----
    {
        const int n0 = wrp * 16;
        float D[2][4][4];
        #pragma unroll
        for (int j = 0; j < 2; j++)
            #pragma unroll
            for (int mt = 0; mt < 4; mt++)
                #pragma unroll
                for (int e = 0; e < 4; e++) D[j][mt][e] = 0.f;

        #pragma unroll 1
        for (int s = 0; s < 8; s++) {
            uint32_t uoff = (uint32_t)(((s * 2 + h16) ^ rl) << 4);
            uint32_t Ah[4][4], Al[4][4];
            #pragma unroll
            for (int mt = 0; mt < 4; mt++) {
                ldm4(Ah[mt], aHiB + mt * 4096 + uoff);
                ldm4(Al[mt], aLoB + mt * 4096 + uoff);
            }
            #pragma unroll
            for (int j = 0; j < 2; j++) {
                uint4 bb = __ldg(&Bpk_g[((48 + wrp * 2 + j) * 8 + s) * 32 + lane]);
                #pragma unroll
                for (int mt = 0; mt < 4; mt++) {
                    mma16816(D[j][mt], Ah[mt], bb.x, bb.y);
                    mma16816(D[j][mt], Al[mt], bb.x, bb.y);
                    mma16816(D[j][mt], Ah[mt], bb.z, bb.w);
                }
            }
        }
        #pragma unroll
        for (int j = 0; j < 2; j++) {
            int c = n0 + j * 8 + (lane & 3) * 2;
            float2 bb = *(const float2*)(proj_b + c);
            #pragma unroll
            for (int mt = 0; mt < 4; mt++) {
                int row = mt * 16 + (lane >> 2);
                float2 o0, o1;
                o0.x = D[j][mt][0] + bb.x;
                o0.y = D[j][mt][1] + bb.y;
                o1.x = D[j][mt][2] + bb.x;
                o1.y = D[j][mt][3] + bb.y;
                *(float2*)(Qs + row * PQ + c)       = o0;
                *(float2*)(Qs + (row + 8) * PQ + c) = o1;
            }
        }
    }
    __syncthreads();

    // ---- Phase 5: reverse-roll scatter (conflict-free LDS.128 + coalesced STG) ----
    float* ob = out + base;
    #pragma unroll
    for (int i = tid; i < 2048; i += 256) {
        int cq = i >> 6, s = i & 63;
        float4 y = *(const float4*)(Qs + s * PQ + cq * 4);
        int sh = ((hn << 3) + (s >> 3) - 4) & 63;
        int sw = ((wn << 3) + (s & 7) - 4) & 63;
        float* po = ob + (cq * 4) * 102400 + sh * 64 + sw;
        po[0]      = y.x;
        po[102400] = y.y;
        po[204800] = y.z;
        po[307200] = y.w;
    }
}

extern "C" void kernel_launch(void* const* d_in, const int* in_sizes, int n_in,
                              void* d_out, int out_size) {
    (void)in_sizes; (void)n_in; (void)out_size;
    prep_w_kernel<<<64, 256>>>((const float*)d_in[1], (const float*)d_in[3]);
    cudaFuncSetAttribute(wattn_kernel, cudaFuncAttributeMaxDynamicSharedMemorySize, SMEM_BYTES);
    wattn_kernel<<<3200, 256, SMEM_BYTES>>>(
        (const float*)d_in[0], (const float*)d_in[2], (const float*)d_in[4],
        (const float*)d_in[5], (float*)d_out);
}

// round 12
// speedup vs baseline: 2.0476x; 1.1854x over previous
#include <cuda_runtime.h>
#include <cuda_bf16.h>
#include <cstdint>

typedef unsigned long long ull;
#define SC_Q 0.17677669529663687f

// ---- smem byte offsets (total ~102KB -> 2 CTAs/SM) ----
#define OFF_T0H 0          // X -> Q -> O  hi bf16 [64][256B] swizzled
#define OFF_T0L 16384      // lo
#define OFF_KH  32768      // K hi
#define OFF_KL  49152
#define OFF_VH  65536      // V hi
#define OFF_VL  81920
#define OFF_BT  98304      // rpb 900 f32
#define OFF_Y   32768      // f32 [64][132] final Y (aliases dead K tile)
#define SMEM_BYTES 101920

__device__ __forceinline__ uint32_t smem_u32(const void* p) {
    uint32_t a;
    asm("{ .reg .u64 t; cvta.to.shared.u64 t, %1; cvt.u32.u64 %0, t; }" : "=r"(a) : "l"(p));
    return a;
}
__device__ __forceinline__ void mma16816(float (&d)[4], const uint32_t (&a)[4], uint32_t b0, uint32_t b1) {
    asm volatile(
        "mma.sync.aligned.m16n8k16.row.col.f32.bf16.bf16.f32 "
        "{%0,%1,%2,%3}, {%4,%5,%6,%7}, {%8,%9}, {%0,%1,%2,%3};"
        : "+f"(d[0]), "+f"(d[1]), "+f"(d[2]), "+f"(d[3])
        : "r"(a[0]), "r"(a[1]), "r"(a[2]), "r"(a[3]), "r"(b0), "r"(b1));
}
__device__ __forceinline__ void ldm4(uint32_t (&a)[4], uint32_t addr) {
    asm volatile("ldmatrix.sync.aligned.m8n8.x4.shared.b16 {%0,%1,%2,%3}, [%4];"
                 : "=r"(a[0]), "=r"(a[1]), "=r"(a[2]), "=r"(a[3]) : "r"(addr));
}
__device__ __forceinline__ void ldm4t(uint32_t (&a)[4], uint32_t addr) {
    asm volatile("ldmatrix.sync.aligned.m8n8.x4.trans.shared.b16 {%0,%1,%2,%3}, [%4];"
                 : "=r"(a[0]), "=r"(a[1]), "=r"(a[2]), "=r"(a[3]) : "r"(addr));
}
__device__ __forceinline__ uint32_t bf2u(__nv_bfloat162 h) {
    uint32_t u; memcpy(&u, &h, 4); return u;
}
// split (v0,v1) -> packed bf16x2 hi + residual lo (.x = even element = low half)
__device__ __forceinline__ void pack_hilo(float v0, float v1, uint32_t &hi, uint32_t &lo) {
    __nv_bfloat162 h2, l2;
    h2.x = __float2bfloat16(v0); h2.y = __float2bfloat16(v1);
    l2.x = __float2bfloat16(v0 - __bfloat162float(h2.x));
    l2.y = __float2bfloat16(v1 - __bfloat162float(h2.y));
    hi = bf2u(h2); lo = bf2u(l2);
}
// tile address: row (0..63), byte-col cb (0..255); 16-unit XOR swizzle
__device__ __forceinline__ uint32_t tadr(int row, int cb) {
    return (uint32_t)row * 256u + (uint32_t)((((cb >> 4) ^ (row & 15)) << 4) + (cb & 15));
}

// Packed B fragments: [n8 0..63][s 0..7][lane] = {bh0,bh1,bl0,bl1}; n8<48 qkv, else proj
__device__ __align__(16) uint4 Bpk_g[64 * 8 * 32];

__global__ void __launch_bounds__(256)
prep_w_kernel(const float* __restrict__ qkv_w, const float* __restrict__ proj_w) {
    int i = blockIdx.x * 256 + threadIdx.x;      // 16384 entries
    int n8 = i >> 8, s = (i >> 5) & 7, lane = i & 31;
    int n = n8 * 8 + (lane >> 2);
    int kb = s * 16 + (lane & 3) * 2;
    const float* src = (n < 384) ? (qkv_w + n * 128) : (proj_w + (n - 384) * 128);
    uint32_t h01, l01, h89, l89;
    pack_hilo(src[kb], src[kb + 1], h01, l01);
    pack_hilo(src[kb + 8], src[kb + 9], h89, l89);
    uint4 o; o.x = h01; o.y = h89; o.z = l01; o.w = l89;
    Bpk_g[i] = o;
}

__global__ void __launch_bounds__(256, 2)
wattn_kernel(const float* __restrict__ x, const float* __restrict__ qkv_b,
             const float* __restrict__ proj_b, const float* __restrict__ rpb,
             float* __restrict__ out)
{
    extern __shared__ char smc[];
    float* Bt = (float*)(smc + OFF_BT);
    float* Yf = (float*)(smc + OFF_Y);

    const int tid = threadIdx.x;
    const int wrp = tid >> 5, lane = tid & 31;
    const uint32_t smb = smem_u32(smc);

    int wid = blockIdx.x;
    const int wn = wid & 7;  wid >>= 3;
    const int hn = wid & 7;  wid >>= 3;
    const int v  = wid % 5;  wid /= 5;
    const int u  = wid % 5;
    const int b  = wid / 5;
    const int base = (((b << 7) * 5 + u) * 5 + v) * 4096;
    const float* xb = x + base;

    // ---- Phase 1: roll+gather X -> swizzled bf16 hi/lo T0 tiles; rpb -> Bt ----
    {
        const int ml = (lane >> 2) & 7, cl = lane & 3;
        const int gm = wrp * 8 + ml;
        const int gsh = ((hn << 3) + (gm >> 3) - 4) & 63;
        const int gsw = ((wn << 3) + (gm & 7) - 4) & 63;
        const float* gp = xb + gsh * 64 + gsw;
        #pragma unroll
        for (int it = 0; it < 16; it++) {
            int cp = it * 4 + cl;
            float v0 = __ldg(gp + (2 * cp) * 102400);
            float v1 = __ldg(gp + (2 * cp + 1) * 102400);
            uint32_t ad = tadr(gm, cp * 4);
            uint32_t hiu, lou;
            pack_hilo(v0, v1, hiu, lou);
            *(uint32_t*)(smc + OFF_T0H + ad) = hiu;
            *(uint32_t*)(smc + OFF_T0L + ad) = lou;
        }
    }
    for (int i = tid; i < 900; i += 256) Bt[i] = rpb[i];
    __syncthreads();

    // ldmatrix A-operand lane geometry (verified in R10/R11)
    const int rl  = ((lane >> 3) & 1) * 8 + (lane & 7);
    const int h16 = (lane >> 4) & 1;
    // B-operand (non-trans) lane geometry: tokens and k-unit
    const int tokB = (lane & 7) + ((lane >> 4) << 3);
    const int kuB  = (lane >> 3) & 1;
    // V-trans lane geometry
    const int tokV = (lane & 7) + (((lane >> 3) & 1) << 3);
    const int duV  = (lane >> 4) & 1;

    // ---- Phase 2: QKV MMA (A = T0 tiles, B = Bpk_g). warp -> 48 n-cols ----
    {
        const int n0 = wrp * 48;
        float D[6][4][4];
        #pragma unroll
        for (int j = 0; j < 6; j++)
            #pragma unroll
            for (int mt = 0; mt < 4; mt++)
                #pragma unroll
                for (int e = 0; e < 4; e++) D[j][mt][e] = 0.f;

        #pragma unroll 1
        for (int s = 0; s < 8; s++) {
            uint32_t uoff = (uint32_t)(((s * 2 + h16) ^ rl) << 4);
            uint32_t A[4][4];
            // hi pass: Ah*Bh + Ah*Bl
            #pragma unroll
            for (int mt = 0; mt < 4; mt++) ldm4(A[mt], smb + OFF_T0H + rl * 256 + mt * 4096 + uoff);
            #pragma unroll
            for (int j = 0; j < 6; j++) {
                uint4 bb = __ldg(&Bpk_g[((wrp * 6 + j) * 8 + s) * 32 + lane]);
                #pragma unroll
                for (int mt = 0; mt < 4; mt++) {
                    mma16816(D[j][mt], A[mt], bb.x, bb.y);
                    mma16816(D[j][mt], A[mt], bb.z, bb.w);
                }
            }
            // lo pass: Al*Bh
            #pragma unroll
            for (int mt = 0; mt < 4; mt++) ldm4(A[mt], smb + OFF_T0L + rl * 256 + mt * 4096 + uoff);
            #pragma unroll
            for (int j = 0; j < 6; j++) {
                uint4 bb = __ldg(&Bpk_g[((wrp * 6 + j) * 8 + s) * 32 + lane]);
                #pragma unroll
                for (int mt = 0; mt < 4; mt++) mma16816(D[j][mt], A[mt], bb.x, bb.y);
            }
        }
        __syncthreads();   // all A-reads of T0 done; safe to overwrite T0 with Q

        // epilogue: remap head-interleaved cols; Q (scaled) -> T0, K -> KT, V -> VT; bf16 hi/lo
        #pragma unroll
        for (int j = 0; j < 6; j++) {
            int c  = n0 + j * 8 + (lane & 3) * 2;
            int hh = c / 96, r = c - hh * 96;
            int seg = r >> 5, col = (hh << 5) + (r & 31);
            int tbH = (seg == 0) ? OFF_T0H : (seg == 1) ? OFF_KH : OFF_VH;
            int tbL = tbH + 16384;
            float sc = (seg == 0) ? SC_Q : 1.0f;
            float b0 = __ldg(qkv_b + c), b1 = __ldg(qkv_b + c + 1);
            #pragma unroll
            for (int mt = 0; mt < 4; mt++) {
                int row = mt * 16 + (lane >> 2);
                uint32_t hiu, lou;
                pack_hilo((D[j][mt][0] + b0) * sc, (D[j][mt][1] + b1) * sc, hiu, lou);
                uint32_t ad = tadr(row, col * 2);
                *(uint32_t*)(smc + tbH + ad) = hiu;
                *(uint32_t*)(smc + tbL + ad) = lou;
                pack_hilo((D[j][mt][2] + b0) * sc, (D[j][mt][3] + b1) * sc, hiu, lou);
                ad = tadr(row + 8, col * 2);
                *(uint32_t*)(smc + tbH + ad) = hiu;
                *(uint32_t*)(smc + tbL + ad) = lou;
            }
        }
    }
    __syncthreads();

    // ---- Phase 3: tensor attention. 16 tasks (head, m-tile); warp w -> tasks w, w+8 ----
    float Oacc[2][4][4];
    #pragma unroll 1
    for (int ti = 0; ti < 2; ti++) {
        const int t = wrp + ti * 8;
        const int h = t >> 2, mt = t & 3;

        float S[8][4];
        #pragma unroll
        for (int t8 = 0; t8 < 8; t8++)
            #pragma unroll
            for (int e = 0; e < 4; e++) S[t8][e] = 0.f;

        uint32_t Qh[2][4], Ql[2][4];
        #pragma unroll
        for (int ks = 0; ks < 2; ks++) {
            uint32_t uo = (uint32_t)(((h * 4 + ks * 2 + h16) ^ rl) << 4);
            ldm4(Qh[ks], smb + OFF_T0H + (mt * 16 + rl) * 256 + uo);
            ldm4(Ql[ks], smb + OFF_T0L + (mt * 16 + rl) * 256 + uo);
        }
        // S = Q K^T (3-term)
        #pragma unroll
        for (int ks = 0; ks < 2; ks++) {
            #pragma unroll
            for (int nb = 0; nb < 4; nb++) {
                int tok = nb * 16 + tokB;
                uint32_t ad = (uint32_t)tok * 256 + (uint32_t)(((h * 4 + ks * 2 + kuB) ^ (tok & 15)) << 4);
                uint32_t Bh[4], Bl[4];
                ldm4(Bh, smb + OFF_KH + ad);
                ldm4(Bl, smb + OFF_KL + ad);
                mma16816(S[2 * nb], Qh[ks], Bh[0], Bh[1]);
                mma16816(S[2 * nb], Ql[ks], Bh[0], Bh[1]);
                mma16816(S[2 * nb], Qh[ks], Bl[0], Bl[1]);
                mma16816(S[2 * nb + 1], Qh[ks], Bh[2], Bh[3]);
                mma16816(S[2 * nb + 1], Ql[ks], Bh[2], Bh[3]);
                mma16816(S[2 * nb + 1], Qh[ks], Bl[2], Bl[3]);
            }
        }
        // + relative position bias
        const int r0g = mt * 16 + (lane >> 2);
        const int cb2 = (lane & 3) * 2;
        #pragma unroll
        for (int t8 = 0; t8 < 8; t8++) {
            #pragma unroll
            for (int e = 0; e < 4; e++) {
                int row = r0g + ((e >> 1) << 3);
                int col = t8 * 8 + cb2 + (e & 1);
                int ridx = ((row >> 3) - (col >> 3) + 7) * 15 + ((row & 7) - (col & 7) + 7);
                S[t8][e] += Bt[ridx * 4 + h];
            }
        }
        // softmax over fragment rows (quad-shfl reduce)
        float m0 = S[0][0], m1 = S[0][2];
        #pragma unroll
        for (int t8 = 0; t8 < 8; t8++) {
            m0 = fmaxf(m0, fmaxf(S[t8][0], S[t8][1]));
            m1 = fmaxf(m1, fmaxf(S[t8][2], S[t8][3]));
        }
        m0 = fmaxf(m0, __shfl_xor_sync(0xffffffffu, m0, 1));
        m0 = fmaxf(m0, __shfl_xor_sync(0xffffffffu, m0, 2));
        m1 = fmaxf(m1, __shfl_xor_sync(0xffffffffu, m1, 1));
        m1 = fmaxf(m1, __shfl_xor_sync(0xffffffffu, m1, 2));
        float l0 = 0.f, l1 = 0.f;
        #pragma unroll
        for (int t8 = 0; t8 < 8; t8++) {
            S[t8][0] = __expf(S[t8][0] - m0); l0 += S[t8][0];
            S[t8][1] = __expf(S[t8][1] - m0); l0 += S[t8][1];
            S[t8][2] = __expf(S[t8][2] - m1); l1 += S[t8][2];
            S[t8][3] = __expf(S[t8][3] - m1); l1 += S[t8][3];
        }
        l0 += __shfl_xor_sync(0xffffffffu, l0, 1);
        l0 += __shfl_xor_sync(0xffffffffu, l0, 2);
        l1 += __shfl_xor_sync(0xffffffffu, l1, 1);
        l1 += __shfl_xor_sync(0xffffffffu, l1, 2);
        float inv0 = __fdividef(1.0f, l0), inv1 = __fdividef(1.0f, l1);

        // O = P V (P in registers; 3-term Ph*Vh + Pl*Vh + Ph*Vl)
        #pragma unroll
        for (int nd = 0; nd < 4; nd++)
            #pragma unroll
            for (int e = 0; e < 4; e++) Oacc[ti][nd][e] = 0.f;
        #pragma unroll
        for (int kt = 0; kt < 4; kt++) {
            uint32_t ph[4], pl[4];
            pack_hilo(S[2 * kt][0], S[2 * kt][1], ph[0], pl[0]);
            pack_hilo(S[2 * kt][2], S[2 * kt][3], ph[1], pl[1]);
            pack_hilo(S[2 * kt + 1][0], S[2 * kt + 1][1], ph[2], pl[2]);
            pack_hilo(S[2 * kt + 1][2], S[2 * kt + 1][3], ph[3], pl[3]);
            #pragma unroll
            for (int db = 0; db < 2; db++) {
                int tok = kt * 16 + tokV;
                uint32_t ad = (uint32_t)tok * 256 +
                              (uint32_t)((((h * 4 + db * 2 + duV)) ^ (tok & 15)) << 4);
                uint32_t Vh[4], Vl[4];
                ldm4t(Vh, smb + OFF_VH + ad);
                ldm4t(Vl, smb + OFF_VL + ad);
                mma16816(Oacc[ti][2 * db], ph, Vh[0], Vh[1]);
                mma16816(Oacc[ti][2 * db], pl, Vh[0], Vh[1]);
                mma16816(Oacc[ti][2 * db], ph, Vl[0], Vl[1]);
                mma16816(Oacc[ti][2 * db + 1], ph, Vh[2], Vh[3]);
                mma16816(Oacc[ti][2 * db + 1], pl, Vh[2], Vh[3]);
                mma16816(Oacc[ti][2 * db + 1], ph, Vl[2], Vl[3]);
            }
        }
        #pragma unroll
        for (int nd = 0; nd < 4; nd++) {
            Oacc[ti][nd][0] *= inv0; Oacc[ti][nd][1] *= inv0;
            Oacc[ti][nd][2] *= inv1; Oacc[ti][nd][3] *= inv1;
        }
    }
    __syncthreads();   // all Q/K/V reads done; overwrite T0 with O

    // write O -> T0 bf16 hi/lo tiles
    #pragma unroll
    for (int ti = 0; ti < 2; ti++) {
        const int t = wrp + ti * 8;
        const int h = t >> 2, mt = t & 3;
        #pragma unroll
        for (int nd = 0; nd < 4; nd++) {
            int col = h * 32 + nd * 8 + (lane & 3) * 2;
            int row = mt * 16 + (lane >> 2);
            uint32_t hiu, lou;
            pack_hilo(Oacc[ti][nd][0], Oacc[ti][nd][1], hiu, lou);
            uint32_t ad = tadr(row, col * 2);
            *(uint32_t*)(smc + OFF_T0H + ad) = hiu;
            *(uint32_t*)(smc + OFF_T0L + ad) = lou;
            pack_hilo(Oacc[ti][nd][2], Oacc[ti][nd][3], hiu, lou);
            ad = tadr(row + 8, col * 2);
            *(uint32_t*)(smc + OFF_T0H + ad) = hiu;
            *(uint32_t*)(smc + OFF_T0L + ad) = lou;
        }
    }
    __syncthreads();

    // ---- Phase 4: proj MMA (A = O tiles, B = Bpk_g rows 48+). Y fp32 -> K region ----
    {
        const int n0 = wrp * 16;
        float D[2][4][4];
        #pragma unroll
        for (int j = 0; j < 2; j++)
            #pragma unroll
            for (int mt = 0; mt < 4; mt++)
                #pragma unroll
                for (int e = 0; e < 4; e++) D[j][mt][e] = 0.f;

        #pragma unroll 1
        for (int s = 0; s < 8; s++) {
            uint32_t uoff = (uint32_t)(((s * 2 + h16) ^ rl) << 4);
            uint32_t Ah[4][4], Al[4][4];
            #pragma unroll
            for (int mt = 0; mt < 4; mt++) {
                ldm4(Ah[mt], smb + OFF_T0H + rl * 256 + mt * 4096 + uoff);
                ldm4(Al[mt], smb + OFF_T0L + rl * 256 + mt * 4096 + uoff);
            }
            #pragma unroll
            for (int j = 0; j < 2; j++) {
                uint4 bb = __ldg(&Bpk_g[((48 + wrp * 2 + j) * 8 + s) * 32 + lane]);
                #pragma unroll
                for (int mt = 0; mt < 4; mt++) {
                    mma16816(D[j][mt], Ah[mt], bb.x, bb.y);
                    mma16816(D[j][mt], Al[mt], bb.x, bb.y);
                    mma16816(D[j][mt], Ah[mt], bb.z, bb.w);
                }
            }
        }
        #pragma unroll
        for (int j = 0; j < 2; j++) {
            int c = n0 + j * 8 + (lane & 3) * 2;
            float2 bb = *(const float2*)(proj_b + c);
            #pragma unroll
            for (int mt = 0; mt < 4; mt++) {
                int row = mt * 16 + (lane >> 2);
                float2 o0, o1;
                o0.x = D[j][mt][0] + bb.x;
                o0.y = D[j][mt][1] + bb.y;
                o1.x = D[j][mt][2] + bb.x;
                o1.y = D[j][mt][3] + bb.y;
                *(float2*)(Yf + row * 132 + c)       = o0;
                *(float2*)(Yf + (row + 8) * 132 + c) = o1;
            }
        }
    }
    __syncthreads();

    // ---- Phase 5: reverse-roll scatter ----
    float* ob = out + base;
    #pragma unroll
    for (int i = tid; i < 2048; i += 256) {
        int cq = i >> 6, s = i & 63;
        float4 y = *(const float4*)(Yf + s * 132 + cq * 4);
        int sh = ((hn << 3) + (s >> 3) - 4) & 63;
        int sw = ((wn << 3) + (s & 7) - 4) & 63;
        float* po = ob + (cq * 4) * 102400 + sh * 64 + sw;
        po[0]      = y.x;
        po[102400] = y.y;
        po[204800] = y.z;
        po[307200] = y.w;
    }
}

extern "C" void kernel_launch(void* const* d_in, const int* in_sizes, int n_in,
                              void* d_out, int out_size) {
    (void)in_sizes; (void)n_in; (void)out_size;
    prep_w_kernel<<<64, 256>>>((const float*)d_in[1], (const float*)d_in[3]);
    cudaFuncSetAttribute(wattn_kernel, cudaFuncAttributeMaxDynamicSharedMemorySize, SMEM_BYTES);
    wattn_kernel<<<3200, 256, SMEM_BYTES>>>(
        (const float*)d_in[0], (const float*)d_in[2], (const float*)d_in[4],
        (const float*)d_in[5], (float*)d_out);
}

// round 13
// speedup vs baseline: 2.9073x; 1.4199x over previous
#include <cuda_runtime.h>
#include <cuda_bf16.h>
#include <cuda_fp16.h>
#include <cstdint>

typedef unsigned long long ull;
#define SC_Q 0.17677669529663687f

// ---- smem byte offsets (total ~102KB -> 2 CTAs/SM) ----
#define OFF_T0H 0          // X -> O  hi (fp16) / Q hi (bf16) [64][256B] swizzled
#define OFF_T0L 16384
#define OFF_KH  32768      // K hi (bf16)
#define OFF_KL  49152
#define OFF_VH  65536      // V hi (bf16)
#define OFF_VL  81920
#define OFF_BT  98304      // rpb 900 f32
#define OFF_Y   32768      // f32 [64][132] final Y (aliases dead K tile)
#define SMEM_BYTES 101920

__device__ __forceinline__ uint32_t smem_u32(const void* p) {
    uint32_t a;
    asm("{ .reg .u64 t; cvta.to.shared.u64 t, %1; cvt.u32.u64 %0, t; }" : "=r"(a) : "l"(p));
    return a;
}
// bf16 MMA (attention, 3-term path)
__device__ __forceinline__ void mma_bf(float (&d)[4], const uint32_t (&a)[4], uint32_t b0, uint32_t b1) {
    asm volatile(
        "mma.sync.aligned.m16n8k16.row.col.f32.bf16.bf16.f32 "
        "{%0,%1,%2,%3}, {%4,%5,%6,%7}, {%8,%9}, {%0,%1,%2,%3};"
        : "+f"(d[0]), "+f"(d[1]), "+f"(d[2]), "+f"(d[3])
        : "r"(a[0]), "r"(a[1]), "r"(a[2]), "r"(a[3]), "r"(b0), "r"(b1));
}
// fp16 MMA (QKV / proj, one-sided split path)
__device__ __forceinline__ void mma_h(float (&d)[4], const uint32_t (&a)[4], uint32_t b0, uint32_t b1) {
    asm volatile(
        "mma.sync.aligned.m16n8k16.row.col.f32.f16.f16.f32 "
        "{%0,%1,%2,%3}, {%4,%5,%6,%7}, {%8,%9}, {%0,%1,%2,%3};"
        : "+f"(d[0]), "+f"(d[1]), "+f"(d[2]), "+f"(d[3])
        : "r"(a[0]), "r"(a[1]), "r"(a[2]), "r"(a[3]), "r"(b0), "r"(b1));
}
__device__ __forceinline__ void ldm4(uint32_t (&a)[4], uint32_t addr) {
    asm volatile("ldmatrix.sync.aligned.m8n8.x4.shared.b16 {%0,%1,%2,%3}, [%4];"
                 : "=r"(a[0]), "=r"(a[1]), "=r"(a[2]), "=r"(a[3]) : "r"(addr));
}
__device__ __forceinline__ void ldm4t(uint32_t (&a)[4], uint32_t addr) {
    asm volatile("ldmatrix.sync.aligned.m8n8.x4.trans.shared.b16 {%0,%1,%2,%3}, [%4];"
                 : "=r"(a[0]), "=r"(a[1]), "=r"(a[2]), "=r"(a[3]) : "r"(addr));
}
__device__ __forceinline__ uint32_t bf2u(__nv_bfloat162 h) {
    uint32_t u; memcpy(&u, &h, 4); return u;
}
__device__ __forceinline__ uint32_t h2u(__half2 h) {
    uint32_t u; memcpy(&u, &h, 4); return u;
}
// bf16 hi + residual lo (attention tiles)
__device__ __forceinline__ void pack_hilo(float v0, float v1, uint32_t &hi, uint32_t &lo) {
    __nv_bfloat162 h2, l2;
    h2.x = __float2bfloat16(v0); h2.y = __float2bfloat16(v1);
    l2.x = __float2bfloat16(v0 - __bfloat162float(h2.x));
    l2.y = __float2bfloat16(v1 - __bfloat162float(h2.y));
    hi = bf2u(h2); lo = bf2u(l2);
}
// fp16 hi + residual lo (X / O tiles for one-sided-split GEMMs)
__device__ __forceinline__ void pack_hilo_h(float v0, float v1, uint32_t &hi, uint32_t &lo) {
    __half2 h2, l2;
    h2.x = __float2half_rn(v0); h2.y = __float2half_rn(v1);
    l2.x = __float2half_rn(v0 - __half2float(h2.x));
    l2.y = __float2half_rn(v1 - __half2float(h2.y));
    hi = h2u(h2); lo = h2u(l2);
}
// tile address: row (0..63), byte-col cb (0..255); 16B-unit XOR swizzle
__device__ __forceinline__ uint32_t tadr(int row, int cb) {
    return (uint32_t)row * 256u + (uint32_t)((((cb >> 4) ^ (row & 15)) << 4) + (cb & 15));
}

// Packed fp16 B fragments: [n8 0..63][s 0..7][lane] = {b0,b1}; n8<48 qkv rows, else proj rows
__device__ __align__(16) uint2 Bpk_g[64 * 8 * 32];

__global__ void __launch_bounds__(256)
prep_w_kernel(const float* __restrict__ qkv_w, const float* __restrict__ proj_w) {
    int i = blockIdx.x * 256 + threadIdx.x;      // 16384 entries
    int n8 = i >> 8, s = (i >> 5) & 7, lane = i & 31;
    int n = n8 * 8 + (lane >> 2);
    int kb = s * 16 + (lane & 3) * 2;
    const float* src = (n < 384) ? (qkv_w + n * 128) : (proj_w + (n - 384) * 128);
    __half2 p0, p1;
    p0.x = __float2half_rn(src[kb]);     p0.y = __float2half_rn(src[kb + 1]);
    p1.x = __float2half_rn(src[kb + 8]); p1.y = __float2half_rn(src[kb + 9]);
    uint2 o; o.x = h2u(p0); o.y = h2u(p1);
    Bpk_g[i] = o;
}

__global__ void __launch_bounds__(256, 2)
wattn_kernel(const float* __restrict__ x, const float* __restrict__ qkv_b,
             const float* __restrict__ proj_b, const float* __restrict__ rpb,
             float* __restrict__ out)
{
    extern __shared__ char smc[];
    float* Bt = (float*)(smc + OFF_BT);
    float* Yf = (float*)(smc + OFF_Y);

    const int tid = threadIdx.x;
    const int wrp = tid >> 5, lane = tid & 31;
    const uint32_t smb = smem_u32(smc);

    int wid = blockIdx.x;
    const int wn = wid & 7;  wid >>= 3;
    const int hn = wid & 7;  wid >>= 3;
    const int v  = wid % 5;  wid /= 5;
    const int u  = wid % 5;
    const int b  = wid / 5;
    const int base = (((b << 7) * 5 + u) * 5 + v) * 4096;
    const float* xb = x + base;

    // ---- Phase 1: roll+gather X -> swizzled fp16 hi/lo T0 tiles; rpb -> Bt ----
    {
        const int ml = (lane >> 2) & 7, cl = lane & 3;
        const int gm = wrp * 8 + ml;
        const int gsh = ((hn << 3) + (gm >> 3) - 4) & 63;
        const int gsw = ((wn << 3) + (gm & 7) - 4) & 63;
        const float* gp = xb + gsh * 64 + gsw;
        #pragma unroll
        for (int it = 0; it < 16; it++) {
            int cp = it * 4 + cl;
            float v0 = __ldg(gp + (2 * cp) * 102400);
            float v1 = __ldg(gp + (2 * cp + 1) * 102400);
            uint32_t ad = tadr(gm, cp * 4);
            uint32_t hiu, lou;
            pack_hilo_h(v0, v1, hiu, lou);
            *(uint32_t*)(smc + OFF_T0H + ad) = hiu;
            *(uint32_t*)(smc + OFF_T0L + ad) = lou;
        }
    }
    for (int i = tid; i < 900; i += 256) Bt[i] = rpb[i];
    __syncthreads();

    // ldmatrix lane geometry (verified)
    const int rl  = ((lane >> 3) & 1) * 8 + (lane & 7);
    const int h16 = (lane >> 4) & 1;
    const int tokB = (lane & 7) + ((lane >> 4) << 3);
    const int kuB  = (lane >> 3) & 1;
    const int tokV = (lane & 7) + (((lane >> 3) & 1) << 3);
    const int duV  = (lane >> 4) & 1;

    // ---- Phase 2: QKV fp16 MMA, one-sided split: (Ah + Al) * B ----
    {
        const int n0 = wrp * 48;
        float D[6][4][4];
        #pragma unroll
        for (int j = 0; j < 6; j++)
            #pragma unroll
            for (int mt = 0; mt < 4; mt++)
                #pragma unroll
                for (int e = 0; e < 4; e++) D[j][mt][e] = 0.f;

        #pragma unroll 1
        for (int s = 0; s < 8; s++) {
            uint32_t uoff = (uint32_t)(((s * 2 + h16) ^ rl) << 4);
            uint32_t A[4][4];
            // hi pass
            #pragma unroll
            for (int mt = 0; mt < 4; mt++) ldm4(A[mt], smb + OFF_T0H + rl * 256 + mt * 4096 + uoff);
            #pragma unroll
            for (int j = 0; j < 6; j++) {
                uint2 bb = __ldg(&Bpk_g[((wrp * 6 + j) * 8 + s) * 32 + lane]);
                #pragma unroll
                for (int mt = 0; mt < 4; mt++) mma_h(D[j][mt], A[mt], bb.x, bb.y);
            }
            // lo pass
            #pragma unroll
            for (int mt = 0; mt < 4; mt++) ldm4(A[mt], smb + OFF_T0L + rl * 256 + mt * 4096 + uoff);
            #pragma unroll
            for (int j = 0; j < 6; j++) {
                uint2 bb = __ldg(&Bpk_g[((wrp * 6 + j) * 8 + s) * 32 + lane]);
                #pragma unroll
                for (int mt = 0; mt < 4; mt++) mma_h(D[j][mt], A[mt], bb.x, bb.y);
            }
        }
        __syncthreads();   // all A-reads of T0 done; safe to overwrite T0 with Q

        // epilogue: remap head-interleaved cols; Q (scaled)->T0, K->KT, V->VT; bf16 hi/lo
        #pragma unroll
        for (int j = 0; j < 6; j++) {
            int c  = n0 + j * 8 + (lane & 3) * 2;
            int hh = c / 96, r = c - hh * 96;
            int seg = r >> 5, col = (hh << 5) + (r & 31);
            int tbH = (seg == 0) ? OFF_T0H : (seg == 1) ? OFF_KH : OFF_VH;
            int tbL = tbH + 16384;
            float sc = (seg == 0) ? SC_Q : 1.0f;
            float b0 = __ldg(qkv_b + c), b1 = __ldg(qkv_b + c + 1);
            #pragma unroll
            for (int mt = 0; mt < 4; mt++) {
                int row = mt * 16 + (lane >> 2);
                uint32_t hiu, lou;
                pack_hilo((D[j][mt][0] + b0) * sc, (D[j][mt][1] + b1) * sc, hiu, lou);
                uint32_t ad = tadr(row, col * 2);
                *(uint32_t*)(smc + tbH + ad) = hiu;
                *(uint32_t*)(smc + tbL + ad) = lou;
                pack_hilo((D[j][mt][2] + b0) * sc, (D[j][mt][3] + b1) * sc, hiu, lou);
                ad = tadr(row + 8, col * 2);
                *(uint32_t*)(smc + tbH + ad) = hiu;
                *(uint32_t*)(smc + tbL + ad) = lou;
            }
        }
    }
    __syncthreads();

    // ---- Phase 3: tensor attention (bf16 3-term). 16 tasks; warp -> tasks w, w+8 ----
    float Oacc[2][4][4];
    #pragma unroll 1
    for (int ti = 0; ti < 2; ti++) {
        const int t = wrp + ti * 8;
        const int h = t >> 2, mt = t & 3;

        float S[8][4];
        #pragma unroll
        for (int t8 = 0; t8 < 8; t8++)
            #pragma unroll
            for (int e = 0; e < 4; e++) S[t8][e] = 0.f;

        uint32_t Qh[2][4], Ql[2][4];
        #pragma unroll
        for (int ks = 0; ks < 2; ks++) {
            uint32_t uo = (uint32_t)(((h * 4 + ks * 2 + h16) ^ rl) << 4);
            ldm4(Qh[ks], smb + OFF_T0H + (mt * 16 + rl) * 256 + uo);
            ldm4(Ql[ks], smb + OFF_T0L + (mt * 16 + rl) * 256 + uo);
        }
        #pragma unroll
        for (int ks = 0; ks < 2; ks++) {
            #pragma unroll
            for (int nb = 0; nb < 4; nb++) {
                int tok = nb * 16 + tokB;
                uint32_t ad = (uint32_t)tok * 256 + (uint32_t)(((h * 4 + ks * 2 + kuB) ^ (tok & 15)) << 4);
                uint32_t Bh[4], Bl[4];
                ldm4(Bh, smb + OFF_KH + ad);
                ldm4(Bl, smb + OFF_KL + ad);
                mma_bf(S[2 * nb], Qh[ks], Bh[0], Bh[1]);
                mma_bf(S[2 * nb], Ql[ks], Bh[0], Bh[1]);
                mma_bf(S[2 * nb], Qh[ks], Bl[0], Bl[1]);
                mma_bf(S[2 * nb + 1], Qh[ks], Bh[2], Bh[3]);
                mma_bf(S[2 * nb + 1], Ql[ks], Bh[2], Bh[3]);
                mma_bf(S[2 * nb + 1], Qh[ks], Bl[2], Bl[3]);
            }
        }
        const int r0g = mt * 16 + (lane >> 2);
        const int cb2 = (lane & 3) * 2;
        #pragma unroll
        for (int t8 = 0; t8 < 8; t8++) {
            #pragma unroll
            for (int e = 0; e < 4; e++) {
                int row = r0g + ((e >> 1) << 3);
                int col = t8 * 8 + cb2 + (e & 1);
                int ridx = ((row >> 3) - (col >> 3) + 7) * 15 + ((row & 7) - (col & 7) + 7);
                S[t8][e] += Bt[ridx * 4 + h];
            }
        }
        float m0 = S[0][0], m1 = S[0][2];
        #pragma unroll
        for (int t8 = 0; t8 < 8; t8++) {
            m0 = fmaxf(m0, fmaxf(S[t8][0], S[t8][1]));
            m1 = fmaxf(m1, fmaxf(S[t8][2], S[t8][3]));
        }
        m0 = fmaxf(m0, __shfl_xor_sync(0xffffffffu, m0, 1));
        m0 = fmaxf(m0, __shfl_xor_sync(0xffffffffu, m0, 2));
        m1 = fmaxf(m1, __shfl_xor_sync(0xffffffffu, m1, 1));
        m1 = fmaxf(m1, __shfl_xor_sync(0xffffffffu, m1, 2));
        float l0 = 0.f, l1 = 0.f;
        #pragma unroll
        for (int t8 = 0; t8 < 8; t8++) {
            S[t8][0] = __expf(S[t8][0] - m0); l0 += S[t8][0];
            S[t8][1] = __expf(S[t8][1] - m0); l0 += S[t8][1];
            S[t8][2] = __expf(S[t8][2] - m1); l1 += S[t8][2];
            S[t8][3] = __expf(S[t8][3] - m1); l1 += S[t8][3];
        }
        l0 += __shfl_xor_sync(0xffffffffu, l0, 1);
        l0 += __shfl_xor_sync(0xffffffffu, l0, 2);
        l1 += __shfl_xor_sync(0xffffffffu, l1, 1);
        l1 += __shfl_xor_sync(0xffffffffu, l1, 2);
        float inv0 = __fdividef(1.0f, l0), inv1 = __fdividef(1.0f, l1);

        #pragma unroll
        for (int nd = 0; nd < 4; nd++)
            #pragma unroll
            for (int e = 0; e < 4; e++) Oacc[ti][nd][e] = 0.f;
        #pragma unroll
        for (int kt = 0; kt < 4; kt++) {
            uint32_t ph[4], pl[4];
            pack_hilo(S[2 * kt][0], S[2 * kt][1], ph[0], pl[0]);
            pack_hilo(S[2 * kt][2], S[2 * kt][3], ph[1], pl[1]);
            pack_hilo(S[2 * kt + 1][0], S[2 * kt + 1][1], ph[2], pl[2]);
            pack_hilo(S[2 * kt + 1][2], S[2 * kt + 1][3], ph[3], pl[3]);
            #pragma unroll
            for (int db = 0; db < 2; db++) {
                int tok = kt * 16 + tokV;
                uint32_t ad = (uint32_t)tok * 256 +
                              (uint32_t)((((h * 4 + db * 2 + duV)) ^ (tok & 15)) << 4);
                uint32_t Vh[4], Vl[4];
                ldm4t(Vh, smb + OFF_VH + ad);
                ldm4t(Vl, smb + OFF_VL + ad);
                mma_bf(Oacc[ti][2 * db], ph, Vh[0], Vh[1]);
                mma_bf(Oacc[ti][2 * db], pl, Vh[0], Vh[1]);
                mma_bf(Oacc[ti][2 * db], ph, Vl[0], Vl[1]);
                mma_bf(Oacc[ti][2 * db + 1], ph, Vh[2], Vh[3]);
                mma_bf(Oacc[ti][2 * db + 1], pl, Vh[2], Vh[3]);
                mma_bf(Oacc[ti][2 * db + 1], ph, Vl[2], Vl[3]);
            }
        }
        #pragma unroll
        for (int nd = 0; nd < 4; nd++) {
            Oacc[ti][nd][0] *= inv0; Oacc[ti][nd][1] *= inv0;
            Oacc[ti][nd][2] *= inv1; Oacc[ti][nd][3] *= inv1;
        }
    }
    __syncthreads();   // all Q/K/V reads done; overwrite T0 with O (fp16 hi/lo)

    #pragma unroll
    for (int ti = 0; ti < 2; ti++) {
        const int t = wrp + ti * 8;
        const int h = t >> 2, mt = t & 3;
        #pragma unroll
        for (int nd = 0; nd < 4; nd++) {
            int col = h * 32 + nd * 8 + (lane & 3) * 2;
            int row = mt * 16 + (lane >> 2);
            uint32_t hiu, lou;
            pack_hilo_h(Oacc[ti][nd][0], Oacc[ti][nd][1], hiu, lou);
            uint32_t ad = tadr(row, col * 2);
            *(uint32_t*)(smc + OFF_T0H + ad) = hiu;
            *(uint32_t*)(smc + OFF_T0L + ad) = lou;
            pack_hilo_h(Oacc[ti][nd][2], Oacc[ti][nd][3], hiu, lou);
            ad = tadr(row + 8, col * 2);
            *(uint32_t*)(smc + OFF_T0H + ad) = hiu;
            *(uint32_t*)(smc + OFF_T0L + ad) = lou;
        }
    }
    __syncthreads();

    // ---- Phase 4: proj fp16 MMA, one-sided split. Y fp32 -> K region ----
    {
        const int n0 = wrp * 16;
        float D[2][4][4];
        #pragma unroll
        for (int j = 0; j < 2; j++)
            #pragma unroll
            for (int mt = 0; mt < 4; mt++)
                #pragma unroll
                for (int e = 0; e < 4; e++) D[j][mt][e] = 0.f;

        #pragma unroll 1
        for (int s = 0; s < 8; s++) {
            uint32_t uoff = (uint32_t)(((s * 2 + h16) ^ rl) << 4);
            uint32_t Ah[4][4], Al[4][4];
            #pragma unroll
            for (int mt = 0; mt < 4; mt++) {
                ldm4(Ah[mt], smb + OFF_T0H + rl * 256 + mt * 4096 + uoff);
                ldm4(Al[mt], smb + OFF_T0L + rl * 256 + mt * 4096 + uoff);
            }
            #pragma unroll
            for (int j = 0; j < 2; j++) {
                uint2 bb = __ldg(&Bpk_g[((48 + wrp * 2 + j) * 8 + s) * 32 + lane]);
                #pragma unroll
                for (int mt = 0; mt < 4; mt++) {
                    mma_h(D[j][mt], Ah[mt], bb.x, bb.y);
                    mma_h(D[j][mt], Al[mt], bb.x, bb.y);
                }
            }
        }
        #pragma unroll
        for (int j = 0; j < 2; j++) {
            int c = n0 + j * 8 + (lane & 3) * 2;
            float2 bb = *(const float2*)(proj_b + c);
            #pragma unroll
            for (int mt = 0; mt < 4; mt++) {
                int row = mt * 16 + (lane >> 2);
                float2 o0, o1;
                o0.x = D[j][mt][0] + bb.x;
                o0.y = D[j][mt][1] + bb.y;
                o1.x = D[j][mt][2] + bb.x;
                o1.y = D[j][mt][3] + bb.y;
                *(float2*)(Yf + row * 132 + c)       = o0;
                *(float2*)(Yf + (row + 8) * 132 + c) = o1;
            }
        }
    }
    __syncthreads();

    // ---- Phase 5: reverse-roll scatter ----
    float* ob = out + base;
    #pragma unroll
    for (int i = tid; i < 2048; i += 256) {
        int cq = i >> 6, s = i & 63;
        float4 y = *(const float4*)(Yf + s * 132 + cq * 4);
        int sh = ((hn << 3) + (s >> 3) - 4) & 63;
        int sw = ((wn << 3) + (s & 7) - 4) & 63;
        float* po = ob + (cq * 4) * 102400 + sh * 64 + sw;
        po[0]      = y.x;
        po[102400] = y.y;
        po[204800] = y.z;
        po[307200] = y.w;
    }
}

extern "C" void kernel_launch(void* const* d_in, const int* in_sizes, int n_in,
                              void* d_out, int out_size) {
    (void)in_sizes; (void)n_in; (void)out_size;
    prep_w_kernel<<<64, 256>>>((const float*)d_in[1], (const float*)d_in[3]);
    cudaFuncSetAttribute(wattn_kernel, cudaFuncAttributeMaxDynamicSharedMemorySize, SMEM_BYTES);
    wattn_kernel<<<3200, 256, SMEM_BYTES>>>(
        (const float*)d_in[0], (const float*)d_in[2], (const float*)d_in[4],
        (const float*)d_in[5], (float*)d_out);
}

// round 14
// speedup vs baseline: 2.9938x; 1.0297x over previous
#include <cuda_runtime.h>
#include <cuda_bf16.h>
#include <cuda_fp16.h>
#include <cstdint>

typedef unsigned long long ull;
#define SC_Q 0.17677669529663687f

// ---- smem byte offsets (~103KB -> 2 CTAs/SM) ----
#define OFF_T0H 0          // X -> Q -> O  hi fp16 [64][256B] swizzled
#define OFF_T0L 16384      // lo
#define OFF_KH  32768      // K fp16 (single)
#define OFF_VH  49152      // V fp16 (single)
#define OFF_Y   65536      // f32 [64][132] final Y
#define OFF_BT  99328      // rpb 900 f32
#define SMEM_BYTES 102928

__device__ __forceinline__ uint32_t smem_u32(const void* p) {
    uint32_t a;
    asm("{ .reg .u64 t; cvta.to.shared.u64 t, %1; cvt.u32.u64 %0, t; }" : "=r"(a) : "l"(p));
    return a;
}
// fp16 MMA (all GEMMs, one-sided split path)
__device__ __forceinline__ void mma_h(float (&d)[4], const uint32_t (&a)[4], uint32_t b0, uint32_t b1) {
    asm volatile(
        "mma.sync.aligned.m16n8k16.row.col.f32.f16.f16.f32 "
        "{%0,%1,%2,%3}, {%4,%5,%6,%7}, {%8,%9}, {%0,%1,%2,%3};"
        : "+f"(d[0]), "+f"(d[1]), "+f"(d[2]), "+f"(d[3])
        : "r"(a[0]), "r"(a[1]), "r"(a[2]), "r"(a[3]), "r"(b0), "r"(b1));
}
__device__ __forceinline__ void ldm4(uint32_t (&a)[4], uint32_t addr) {
    asm volatile("ldmatrix.sync.aligned.m8n8.x4.shared.b16 {%0,%1,%2,%3}, [%4];"
                 : "=r"(a[0]), "=r"(a[1]), "=r"(a[2]), "=r"(a[3]) : "r"(addr));
}
__device__ __forceinline__ void ldm4t(uint32_t (&a)[4], uint32_t addr) {
    asm volatile("ldmatrix.sync.aligned.m8n8.x4.trans.shared.b16 {%0,%1,%2,%3}, [%4];"
                 : "=r"(a[0]), "=r"(a[1]), "=r"(a[2]), "=r"(a[3]) : "r"(addr));
}
__device__ __forceinline__ uint32_t h2u(__half2 h) {
    uint32_t u; memcpy(&u, &h, 4); return u;
}
// fp16 hi + residual lo
__device__ __forceinline__ void pack_hilo_h(float v0, float v1, uint32_t &hi, uint32_t &lo) {
    __half2 h2, l2;
    h2.x = __float2half_rn(v0); h2.y = __float2half_rn(v1);
    l2.x = __float2half_rn(v0 - __half2float(h2.x));
    l2.y = __float2half_rn(v1 - __half2float(h2.y));
    hi = h2u(h2); lo = h2u(l2);
}
// fp16 single pack
__device__ __forceinline__ uint32_t pack_h(float v0, float v1) {
    __half2 h2;
    h2.x = __float2half_rn(v0); h2.y = __float2half_rn(v1);
    return h2u(h2);
}
// tile address: row (0..63), byte-col cb (0..255); 16B-unit XOR swizzle
__device__ __forceinline__ uint32_t tadr(int row, int cb) {
    return (uint32_t)row * 256u + (uint32_t)((((cb >> 4) ^ (row & 15)) << 4) + (cb & 15));
}

// Packed fp16 B fragments: [n8 0..63][s 0..7][lane] = {b0,b1}; n8<48 qkv rows, else proj rows
__device__ __align__(16) uint2 Bpk_g[64 * 8 * 32];

__global__ void __launch_bounds__(256)
prep_w_kernel(const float* __restrict__ qkv_w, const float* __restrict__ proj_w) {
    int i = blockIdx.x * 256 + threadIdx.x;      // 16384 entries
    int n8 = i >> 8, s = (i >> 5) & 7, lane = i & 31;
    int n = n8 * 8 + (lane >> 2);
    int kb = s * 16 + (lane & 3) * 2;
    const float* src = (n < 384) ? (qkv_w + n * 128) : (proj_w + (n - 384) * 128);
    uint2 o;
    o.x = pack_h(src[kb], src[kb + 1]);
    o.y = pack_h(src[kb + 8], src[kb + 9]);
    Bpk_g[i] = o;
}

__global__ void __launch_bounds__(256, 2)
wattn_kernel(const float* __restrict__ x, const float* __restrict__ qkv_b,
             const float* __restrict__ proj_b, const float* __restrict__ rpb,
             float* __restrict__ out)
{
    extern __shared__ char smc[];
    float* Bt = (float*)(smc + OFF_BT);
    float* Yf = (float*)(smc + OFF_Y);

    const int tid = threadIdx.x;
    const int wrp = tid >> 5, lane = tid & 31;
    const uint32_t smb = smem_u32(smc);

    int wid = blockIdx.x;
    const int wn = wid & 7;  wid >>= 3;
    const int hn = wid & 7;  wid >>= 3;
    const int v  = wid % 5;  wid /= 5;
    const int u  = wid % 5;
    const int b  = wid / 5;
    const int base = (((b << 7) * 5 + u) * 5 + v) * 4096;
    const float* xb = x + base;

    // ---- Phase 1: roll+gather X -> swizzled fp16 hi/lo T0 tiles; rpb -> Bt ----
    {
        const int ml = (lane >> 2) & 7, cl = lane & 3;
        const int gm = wrp * 8 + ml;
        const int gsh = ((hn << 3) + (gm >> 3) - 4) & 63;
        const int gsw = ((wn << 3) + (gm & 7) - 4) & 63;
        const float* gp = xb + gsh * 64 + gsw;
        #pragma unroll
        for (int it = 0; it < 16; it++) {
            int cp = it * 4 + cl;
            float v0 = __ldg(gp + (2 * cp) * 102400);
            float v1 = __ldg(gp + (2 * cp + 1) * 102400);
            uint32_t ad = tadr(gm, cp * 4);
            uint32_t hiu, lou;
            pack_hilo_h(v0, v1, hiu, lou);
            *(uint32_t*)(smc + OFF_T0H + ad) = hiu;
            *(uint32_t*)(smc + OFF_T0L + ad) = lou;
        }
    }
    for (int i = tid; i < 900; i += 256) Bt[i] = rpb[i];
    __syncthreads();

    // ldmatrix lane geometry (verified)
    const int rl  = ((lane >> 3) & 1) * 8 + (lane & 7);
    const int h16 = (lane >> 4) & 1;
    const int tokB = (lane & 7) + ((lane >> 4) << 3);
    const int kuB  = (lane >> 3) & 1;
    const int tokV = (lane & 7) + (((lane >> 3) & 1) << 3);
    const int duV  = (lane >> 4) & 1;

    // ---- Phase 2: QKV fp16 MMA, one-sided split: (Ah + Al) * B ----
    {
        const int n0 = wrp * 48;
        float D[6][4][4];
        #pragma unroll
        for (int j = 0; j < 6; j++)
            #pragma unroll
            for (int mt = 0; mt < 4; mt++)
                #pragma unroll
                for (int e = 0; e < 4; e++) D[j][mt][e] = 0.f;

        #pragma unroll 1
        for (int s = 0; s < 8; s++) {
            uint32_t uoff = (uint32_t)(((s * 2 + h16) ^ rl) << 4);
            uint32_t A[4][4];
            // hi pass
            #pragma unroll
            for (int mt = 0; mt < 4; mt++) ldm4(A[mt], smb + OFF_T0H + rl * 256 + mt * 4096 + uoff);
            #pragma unroll
            for (int j = 0; j < 6; j++) {
                uint2 bb = __ldg(&Bpk_g[((wrp * 6 + j) * 8 + s) * 32 + lane]);
                #pragma unroll
                for (int mt = 0; mt < 4; mt++) mma_h(D[j][mt], A[mt], bb.x, bb.y);
            }
            // lo pass
            #pragma unroll
            for (int mt = 0; mt < 4; mt++) ldm4(A[mt], smb + OFF_T0L + rl * 256 + mt * 4096 + uoff);
            #pragma unroll
            for (int j = 0; j < 6; j++) {
                uint2 bb = __ldg(&Bpk_g[((wrp * 6 + j) * 8 + s) * 32 + lane]);
                #pragma unroll
                for (int mt = 0; mt < 4; mt++) mma_h(D[j][mt], A[mt], bb.x, bb.y);
            }
        }
        __syncthreads();   // all A-reads of T0 done; safe to overwrite T0 with Q

        // epilogue: remap head-interleaved cols; Q (scaled, split)->T0, K/V (single fp16)->KH/VH
        #pragma unroll
        for (int j = 0; j < 6; j++) {
            int c  = n0 + j * 8 + (lane & 3) * 2;
            int hh = c / 96, r = c - hh * 96;
            int seg = r >> 5, col = (hh << 5) + (r & 31);
            float b0 = __ldg(qkv_b + c), b1 = __ldg(qkv_b + c + 1);
            if (seg == 0) {
                #pragma unroll
                for (int mt = 0; mt < 4; mt++) {
                    int row = mt * 16 + (lane >> 2);
                    uint32_t hiu, lou;
                    pack_hilo_h((D[j][mt][0] + b0) * SC_Q, (D[j][mt][1] + b1) * SC_Q, hiu, lou);
                    uint32_t ad = tadr(row, col * 2);
                    *(uint32_t*)(smc + OFF_T0H + ad) = hiu;
                    *(uint32_t*)(smc + OFF_T0L + ad) = lou;
                    pack_hilo_h((D[j][mt][2] + b0) * SC_Q, (D[j][mt][3] + b1) * SC_Q, hiu, lou);
                    ad = tadr(row + 8, col * 2);
                    *(uint32_t*)(smc + OFF_T0H + ad) = hiu;
                    *(uint32_t*)(smc + OFF_T0L + ad) = lou;
                }
            } else {
                int tb = (seg == 1) ? OFF_KH : OFF_VH;
                #pragma unroll
                for (int mt = 0; mt < 4; mt++) {
                    int row = mt * 16 + (lane >> 2);
                    *(uint32_t*)(smc + tb + tadr(row, col * 2)) =
                        pack_h(D[j][mt][0] + b0, D[j][mt][1] + b1);
                    *(uint32_t*)(smc + tb + tadr(row + 8, col * 2)) =
                        pack_h(D[j][mt][2] + b0, D[j][mt][3] + b1);
                }
            }
        }
    }
    __syncthreads();

    // ---- Phase 3: tensor attention (fp16, one-sided split). 16 tasks; warp -> w, w+8 ----
    float Oacc[2][4][4];
    #pragma unroll 1
    for (int ti = 0; ti < 2; ti++) {
        const int t = wrp + ti * 8;
        const int h = t >> 2, mt = t & 3;

        float S[8][4];
        #pragma unroll
        for (int t8 = 0; t8 < 8; t8++)
            #pragma unroll
            for (int e = 0; e < 4; e++) S[t8][e] = 0.f;

        uint32_t Qh[2][4], Ql[2][4];
        #pragma unroll
        for (int ks = 0; ks < 2; ks++) {
            uint32_t uo = (uint32_t)(((h * 4 + ks * 2 + h16) ^ rl) << 4);
            ldm4(Qh[ks], smb + OFF_T0H + (mt * 16 + rl) * 256 + uo);
            ldm4(Ql[ks], smb + OFF_T0L + (mt * 16 + rl) * 256 + uo);
        }
        // S = (Qh + Ql) K^T, K single fp16
        #pragma unroll
        for (int ks = 0; ks < 2; ks++) {
            #pragma unroll
            for (int nb = 0; nb < 4; nb++) {
                int tok = nb * 16 + tokB;
                uint32_t ad = (uint32_t)tok * 256 + (uint32_t)(((h * 4 + ks * 2 + kuB) ^ (tok & 15)) << 4);
                uint32_t Bh[4];
                ldm4(Bh, smb + OFF_KH + ad);
                mma_h(S[2 * nb], Qh[ks], Bh[0], Bh[1]);
                mma_h(S[2 * nb], Ql[ks], Bh[0], Bh[1]);
                mma_h(S[2 * nb + 1], Qh[ks], Bh[2], Bh[3]);
                mma_h(S[2 * nb + 1], Ql[ks], Bh[2], Bh[3]);
            }
        }
        // + relative position bias
        const int r0g = mt * 16 + (lane >> 2);
        const int cb2 = (lane & 3) * 2;
        #pragma unroll
        for (int t8 = 0; t8 < 8; t8++) {
            #pragma unroll
            for (int e = 0; e < 4; e++) {
                int row = r0g + ((e >> 1) << 3);
                int col = t8 * 8 + cb2 + (e & 1);
                int ridx = ((row >> 3) - (col >> 3) + 7) * 15 + ((row & 7) - (col & 7) + 7);
                S[t8][e] += Bt[ridx * 4 + h];
            }
        }
        // softmax over fragment rows (quad-shfl reduce)
        float m0 = S[0][0], m1 = S[0][2];
        #pragma unroll
        for (int t8 = 0; t8 < 8; t8++) {
            m0 = fmaxf(m0, fmaxf(S[t8][0], S[t8][1]));
            m1 = fmaxf(m1, fmaxf(S[t8][2], S[t8][3]));
        }
        m0 = fmaxf(m0, __shfl_xor_sync(0xffffffffu, m0, 1));
        m0 = fmaxf(m0, __shfl_xor_sync(0xffffffffu, m0, 2));
        m1 = fmaxf(m1, __shfl_xor_sync(0xffffffffu, m1, 1));
        m1 = fmaxf(m1, __shfl_xor_sync(0xffffffffu, m1, 2));
        float l0 = 0.f, l1 = 0.f;
        #pragma unroll
        for (int t8 = 0; t8 < 8; t8++) {
            S[t8][0] = __expf(S[t8][0] - m0); l0 += S[t8][0];
            S[t8][1] = __expf(S[t8][1] - m0); l0 += S[t8][1];
            S[t8][2] = __expf(S[t8][2] - m1); l1 += S[t8][2];
            S[t8][3] = __expf(S[t8][3] - m1); l1 += S[t8][3];
        }
        l0 += __shfl_xor_sync(0xffffffffu, l0, 1);
        l0 += __shfl_xor_sync(0xffffffffu, l0, 2);
        l1 += __shfl_xor_sync(0xffffffffu, l1, 1);
        l1 += __shfl_xor_sync(0xffffffffu, l1, 2);
        float inv0 = __fdividef(1.0f, l0), inv1 = __fdividef(1.0f, l1);

        // O = (Ph + Pl) V, V single fp16
        #pragma unroll
        for (int nd = 0; nd < 4; nd++)
            #pragma unroll
            for (int e = 0; e < 4; e++) Oacc[ti][nd][e] = 0.f;
        #pragma unroll
        for (int kt = 0; kt < 4; kt++) {
            uint32_t ph[4], pl[4];
            pack_hilo_h(S[2 * kt][0], S[2 * kt][1], ph[0], pl[0]);
            pack_hilo_h(S[2 * kt][2], S[2 * kt][3], ph[1], pl[1]);
            pack_hilo_h(S[2 * kt + 1][0], S[2 * kt + 1][1], ph[2], pl[2]);
            pack_hilo_h(S[2 * kt + 1][2], S[2 * kt + 1][3], ph[3], pl[3]);
            #pragma unroll
            for (int db = 0; db < 2; db++) {
                int tok = kt * 16 + tokV;
                uint32_t ad = (uint32_t)tok * 256 +
                              (uint32_t)((((h * 4 + db * 2 + duV)) ^ (tok & 15)) << 4);
                uint32_t Vh[4];
                ldm4t(Vh, smb + OFF_VH + ad);
                mma_h(Oacc[ti][2 * db], ph, Vh[0], Vh[1]);
                mma_h(Oacc[ti][2 * db], pl, Vh[0], Vh[1]);
                mma_h(Oacc[ti][2 * db + 1], ph, Vh[2], Vh[3]);
                mma_h(Oacc[ti][2 * db + 1], pl, Vh[2], Vh[3]);
            }
        }
        #pragma unroll
        for (int nd = 0; nd < 4; nd++) {
            Oacc[ti][nd][0] *= inv0; Oacc[ti][nd][1] *= inv0;
            Oacc[ti][nd][2] *= inv1; Oacc[ti][nd][3] *= inv1;
        }
    }
    __syncthreads();   // all Q/K/V reads done; overwrite T0 with O (fp16 hi/lo)

    #pragma unroll
    for (int ti = 0; ti < 2; ti++) {
        const int t = wrp + ti * 8;
        const int h = t >> 2, mt = t & 3;
        #pragma unroll
        for (int nd = 0; nd < 4; nd++) {
            int col = h * 32 + nd * 8 + (lane & 3) * 2;
            int row = mt * 16 + (lane >> 2);
            uint32_t hiu, lou;
            pack_hilo_h(Oacc[ti][nd][0], Oacc[ti][nd][1], hiu, lou);
            uint32_t ad = tadr(row, col * 2);
            *(uint32_t*)(smc + OFF_T0H + ad) = hiu;
            *(uint32_t*)(smc + OFF_T0L + ad) = lou;
            pack_hilo_h(Oacc[ti][nd][2], Oacc[ti][nd][3], hiu, lou);
            ad = tadr(row + 8, col * 2);
            *(uint32_t*)(smc + OFF_T0H + ad) = hiu;
            *(uint32_t*)(smc + OFF_T0L + ad) = lou;
        }
    }
    __syncthreads();

    // ---- Phase 4: proj fp16 MMA, one-sided split. Y fp32 -> OFF_Y ----
    {
        const int n0 = wrp * 16;
        float D[2][4][4];
        #pragma unroll
        for (int j = 0; j < 2; j++)
            #pragma unroll
            for (int mt = 0; mt < 4; mt++)
                #pragma unroll
                for (int e = 0; e < 4; e++) D[j][mt][e] = 0.f;

        #pragma unroll 1
        for (int s = 0; s < 8; s++) {
            uint32_t uoff = (uint32_t)(((s * 2 + h16) ^ rl) << 4);
            uint32_t Ah[4][4], Al[4][4];
            #pragma unroll
            for (int mt = 0; mt < 4; mt++) {
                ldm4(Ah[mt], smb + OFF_T0H + rl * 256 + mt * 4096 + uoff);
                ldm4(Al[mt], smb + OFF_T0L + rl * 256 + mt * 4096 + uoff);
            }
            #pragma unroll
            for (int j = 0; j < 2; j++) {
                uint2 bb = __ldg(&Bpk_g[((48 + wrp * 2 + j) * 8 + s) * 32 + lane]);
                #pragma unroll
                for (int mt = 0; mt < 4; mt++) {
                    mma_h(D[j][mt], Ah[mt], bb.x, bb.y);
                    mma_h(D[j][mt], Al[mt], bb.x, bb.y);
                }
            }
        }
        #pragma unroll
        for (int j = 0; j < 2; j++) {
            int c = n0 + j * 8 + (lane & 3) * 2;
            float2 bb = *(const float2*)(proj_b + c);
            #pragma unroll
            for (int mt = 0; mt < 4; mt++) {
                int row = mt * 16 + (lane >> 2);
                float2 o0, o1;
                o0.x = D[j][mt][0] + bb.x;
                o0.y = D[j][mt][1] + bb.y;
                o1.x = D[j][mt][2] + bb.x;
                o1.y = D[j][mt][3] + bb.y;
                *(float2*)(Yf + row * 132 + c)       = o0;
                *(float2*)(Yf + (row + 8) * 132 + c) = o1;
            }
        }
    }
    __syncthreads();

    // ---- Phase 5: reverse-roll scatter ----
    float* ob = out + base;
    #pragma unroll
    for (int i = tid; i < 2048; i += 256) {
        int cq = i >> 6, s = i & 63;
        float4 y = *(const float4*)(Yf + s * 132 + cq * 4);
        int sh = ((hn << 3) + (s >> 3) - 4) & 63;
        int sw = ((wn << 3) + (s & 7) - 4) & 63;
        float* po = ob + (cq * 4) * 102400 + sh * 64 + sw;
        po[0]      = y.x;
        po[102400] = y.y;
        po[204800] = y.z;
        po[307200] = y.w;
    }
}

extern "C" void kernel_launch(void* const* d_in, const int* in_sizes, int n_in,
                              void* d_out, int out_size) {
    (void)in_sizes; (void)n_in; (void)out_size;
    prep_w_kernel<<<64, 256>>>((const float*)d_in[1], (const float*)d_in[3]);
    cudaFuncSetAttribute(wattn_kernel, cudaFuncAttributeMaxDynamicSharedMemorySize, SMEM_BYTES);
    wattn_kernel<<<3200, 256, SMEM_BYTES>>>(
        (const float*)d_in[0], (const float*)d_in[2], (const float*)d_in[4],
        (const float*)d_in[5], (float*)d_out);
}

// round 15
// speedup vs baseline: 3.4790x; 1.1621x over previous
#include <cuda_runtime.h>
#include <cuda_bf16.h>
#include <cuda_fp16.h>
#include <cstdint>

typedef unsigned long long ull;
#define SC_Q 0.17677669529663687f

// ---- smem byte offsets (~103KB -> 2 CTAs/SM) ----
#define OFF_T0H 0          // X -> Q -> O  hi fp16 [64][256B] swizzled
#define OFF_T0L 16384      // lo (Q/O residual; unused for X)
#define OFF_KH  32768      // K fp16 (single)
#define OFF_VH  49152      // V fp16 (single)
#define OFF_Y   65536      // f32 [64][132] final Y
#define OFF_BT  99328      // rpb 900 f32
#define SMEM_BYTES 102928

__device__ __forceinline__ uint32_t smem_u32(const void* p) {
    uint32_t a;
    asm("{ .reg .u64 t; cvta.to.shared.u64 t, %1; cvt.u32.u64 %0, t; }" : "=r"(a) : "l"(p));
    return a;
}
// fp16 MMA
__device__ __forceinline__ void mma_h(float (&d)[4], const uint32_t (&a)[4], uint32_t b0, uint32_t b1) {
    asm volatile(
        "mma.sync.aligned.m16n8k16.row.col.f32.f16.f16.f32 "
        "{%0,%1,%2,%3}, {%4,%5,%6,%7}, {%8,%9}, {%0,%1,%2,%3};"
        : "+f"(d[0]), "+f"(d[1]), "+f"(d[2]), "+f"(d[3])
        : "r"(a[0]), "r"(a[1]), "r"(a[2]), "r"(a[3]), "r"(b0), "r"(b1));
}
__device__ __forceinline__ void ldm4(uint32_t (&a)[4], uint32_t addr) {
    asm volatile("ldmatrix.sync.aligned.m8n8.x4.shared.b16 {%0,%1,%2,%3}, [%4];"
                 : "=r"(a[0]), "=r"(a[1]), "=r"(a[2]), "=r"(a[3]) : "r"(addr));
}
__device__ __forceinline__ void ldm4t(uint32_t (&a)[4], uint32_t addr) {
    asm volatile("ldmatrix.sync.aligned.m8n8.x4.trans.shared.b16 {%0,%1,%2,%3}, [%4];"
                 : "=r"(a[0]), "=r"(a[1]), "=r"(a[2]), "=r"(a[3]) : "r"(addr));
}
__device__ __forceinline__ uint32_t h2u(__half2 h) {
    uint32_t u; memcpy(&u, &h, 4); return u;
}
// fp16 hi + residual lo
__device__ __forceinline__ void pack_hilo_h(float v0, float v1, uint32_t &hi, uint32_t &lo) {
    __half2 h2, l2;
    h2.x = __float2half_rn(v0); h2.y = __float2half_rn(v1);
    l2.x = __float2half_rn(v0 - __half2float(h2.x));
    l2.y = __float2half_rn(v1 - __half2float(h2.y));
    hi = h2u(h2); lo = h2u(l2);
}
// fp16 single pack
__device__ __forceinline__ uint32_t pack_h(float v0, float v1) {
    __half2 h2;
    h2.x = __float2half_rn(v0); h2.y = __float2half_rn(v1);
    return h2u(h2);
}
// tile address: row (0..63), byte-col cb (0..255); 16B-unit XOR swizzle
__device__ __forceinline__ uint32_t tadr(int row, int cb) {
    return (uint32_t)row * 256u + (uint32_t)((((cb >> 4) ^ (row & 15)) << 4) + (cb & 15));
}

// Packed fp16 B fragments: [n8 0..63][s 0..7][lane] = {b0,b1}; n8<48 qkv rows, else proj rows
__device__ __align__(16) uint2 Bpk_g[64 * 8 * 32];

__global__ void __launch_bounds__(256)
prep_w_kernel(const float* __restrict__ qkv_w, const float* __restrict__ proj_w) {
    int i = blockIdx.x * 256 + threadIdx.x;      // 16384 entries
    int n8 = i >> 8, s = (i >> 5) & 7, lane = i & 31;
    int n = n8 * 8 + (lane >> 2);
    int kb = s * 16 + (lane & 3) * 2;
    const float* src = (n < 384) ? (qkv_w + n * 128) : (proj_w + (n - 384) * 128);
    uint2 o;
    o.x = pack_h(src[kb], src[kb + 1]);
    o.y = pack_h(src[kb + 8], src[kb + 9]);
    Bpk_g[i] = o;
}

__global__ void __launch_bounds__(256, 2)
wattn_kernel(const float* __restrict__ x, const float* __restrict__ qkv_b,
             const float* __restrict__ proj_b, const float* __restrict__ rpb,
             float* __restrict__ out)
{
    extern __shared__ char smc[];
    float* Bt = (float*)(smc + OFF_BT);
    float* Yf = (float*)(smc + OFF_Y);

    const int tid = threadIdx.x;
    const int wrp = tid >> 5, lane = tid & 31;
    const uint32_t smb = smem_u32(smc);

    int wid = blockIdx.x;
    const int wn = wid & 7;  wid >>= 3;
    const int hn = wid & 7;  wid >>= 3;
    const int v  = wid % 5;  wid /= 5;
    const int u  = wid % 5;
    const int b  = wid / 5;
    const int base = (((b << 7) * 5 + u) * 5 + v) * 4096;
    const float* xb = x + base;

    // ---- Phase 1: roll+gather X -> swizzled fp16 (single) T0H tile; rpb -> Bt ----
    {
        const int ml = (lane >> 2) & 7, cl = lane & 3;
        const int gm = wrp * 8 + ml;
        const int gsh = ((hn << 3) + (gm >> 3) - 4) & 63;
        const int gsw = ((wn << 3) + (gm & 7) - 4) & 63;
        const float* gp = xb + gsh * 64 + gsw;
        #pragma unroll
        for (int it = 0; it < 16; it++) {
            int cp = it * 4 + cl;
            float v0 = __ldg(gp + (2 * cp) * 102400);
            float v1 = __ldg(gp + (2 * cp + 1) * 102400);
            *(uint32_t*)(smc + OFF_T0H + tadr(gm, cp * 4)) = pack_h(v0, v1);
        }
    }
    for (int i = tid; i < 900; i += 256) Bt[i] = rpb[i];
    __syncthreads();

    // ldmatrix lane geometry (verified)
    const int rl  = ((lane >> 3) & 1) * 8 + (lane & 7);
    const int h16 = (lane >> 4) & 1;
    const int tokB = (lane & 7) + ((lane >> 4) << 3);
    const int kuB  = (lane >> 3) & 1;
    const int tokV = (lane & 7) + (((lane >> 3) & 1) << 3);
    const int duV  = (lane >> 4) & 1;

    // ---- Phase 2: QKV fp16 MMA, single-precision-A (X fp16): A * B ----
    {
        const int n0 = wrp * 48;
        float D[6][4][4];
        #pragma unroll
        for (int j = 0; j < 6; j++)
            #pragma unroll
            for (int mt = 0; mt < 4; mt++)
                #pragma unroll
                for (int e = 0; e < 4; e++) D[j][mt][e] = 0.f;

        #pragma unroll 1
        for (int s = 0; s < 8; s++) {
            uint32_t uoff = (uint32_t)(((s * 2 + h16) ^ rl) << 4);
            uint32_t A[4][4];
            #pragma unroll
            for (int mt = 0; mt < 4; mt++) ldm4(A[mt], smb + OFF_T0H + rl * 256 + mt * 4096 + uoff);
            #pragma unroll
            for (int j = 0; j < 6; j++) {
                uint2 bb = __ldg(&Bpk_g[((wrp * 6 + j) * 8 + s) * 32 + lane]);
                #pragma unroll
                for (int mt = 0; mt < 4; mt++) mma_h(D[j][mt], A[mt], bb.x, bb.y);
            }
        }
        __syncthreads();   // all A-reads of T0 done; safe to overwrite T0 with Q

        // epilogue: remap head-interleaved cols; Q (scaled, split)->T0H/T0L, K/V (single)->KH/VH
        #pragma unroll
        for (int j = 0; j < 6; j++) {
            int c  = n0 + j * 8 + (lane & 3) * 2;
            int hh = c / 96, r = c - hh * 96;
            int seg = r >> 5, col = (hh << 5) + (r & 31);
            float b0 = __ldg(qkv_b + c), b1 = __ldg(qkv_b + c + 1);
            if (seg == 0) {
                #pragma unroll
                for (int mt = 0; mt < 4; mt++) {
                    int row = mt * 16 + (lane >> 2);
                    uint32_t hiu, lou;
                    pack_hilo_h((D[j][mt][0] + b0) * SC_Q, (D[j][mt][1] + b1) * SC_Q, hiu, lou);
                    uint32_t ad = tadr(row, col * 2);
                    *(uint32_t*)(smc + OFF_T0H + ad) = hiu;
                    *(uint32_t*)(smc + OFF_T0L + ad) = lou;
                    pack_hilo_h((D[j][mt][2] + b0) * SC_Q, (D[j][mt][3] + b1) * SC_Q, hiu, lou);
                    ad = tadr(row + 8, col * 2);
                    *(uint32_t*)(smc + OFF_T0H + ad) = hiu;
                    *(uint32_t*)(smc + OFF_T0L + ad) = lou;
                }
            } else {
                int tb = (seg == 1) ? OFF_KH : OFF_VH;
                #pragma unroll
                for (int mt = 0; mt < 4; mt++) {
                    int row = mt * 16 + (lane >> 2);
                    *(uint32_t*)(smc + tb + tadr(row, col * 2)) =
                        pack_h(D[j][mt][0] + b0, D[j][mt][1] + b1);
                    *(uint32_t*)(smc + tb + tadr(row + 8, col * 2)) =
                        pack_h(D[j][mt][2] + b0, D[j][mt][3] + b1);
                }
            }
        }
    }
    __syncthreads();

    // ---- Phase 3: tensor attention (fp16, Q/P split). 16 tasks; warp -> w, w+8 ----
    float Oacc[2][4][4];
    #pragma unroll 1
    for (int ti = 0; ti < 2; ti++) {
        const int t = wrp + ti * 8;
        const int h = t >> 2, mt = t & 3;

        float S[8][4];
        #pragma unroll
        for (int t8 = 0; t8 < 8; t8++)
            #pragma unroll
            for (int e = 0; e < 4; e++) S[t8][e] = 0.f;

        uint32_t Qh[2][4], Ql[2][4];
        #pragma unroll
        for (int ks = 0; ks < 2; ks++) {
            uint32_t uo = (uint32_t)(((h * 4 + ks * 2 + h16) ^ rl) << 4);
            ldm4(Qh[ks], smb + OFF_T0H + (mt * 16 + rl) * 256 + uo);
            ldm4(Ql[ks], smb + OFF_T0L + (mt * 16 + rl) * 256 + uo);
        }
        // S = (Qh + Ql) K^T, K single fp16
        #pragma unroll
        for (int ks = 0; ks < 2; ks++) {
            #pragma unroll
            for (int nb = 0; nb < 4; nb++) {
                int tok = nb * 16 + tokB;
                uint32_t ad = (uint32_t)tok * 256 + (uint32_t)(((h * 4 + ks * 2 + kuB) ^ (tok & 15)) << 4);
                uint32_t Bh[4];
                ldm4(Bh, smb + OFF_KH + ad);
                mma_h(S[2 * nb], Qh[ks], Bh[0], Bh[1]);
                mma_h(S[2 * nb], Ql[ks], Bh[0], Bh[1]);
                mma_h(S[2 * nb + 1], Qh[ks], Bh[2], Bh[3]);
                mma_h(S[2 * nb + 1], Ql[ks], Bh[2], Bh[3]);
            }
        }
        // + relative position bias
        const int r0g = mt * 16 + (lane >> 2);
        const int cb2 = (lane & 3) * 2;
        #pragma unroll
        for (int t8 = 0; t8 < 8; t8++) {
            #pragma unroll
            for (int e = 0; e < 4; e++) {
                int row = r0g + ((e >> 1) << 3);
                int col = t8 * 8 + cb2 + (e & 1);
                int ridx = ((row >> 3) - (col >> 3) + 7) * 15 + ((row & 7) - (col & 7) + 7);
                S[t8][e] += Bt[ridx * 4 + h];
            }
        }
        // softmax over fragment rows (quad-shfl reduce)
        float m0 = S[0][0], m1 = S[0][2];
        #pragma unroll
        for (int t8 = 0; t8 < 8; t8++) {
            m0 = fmaxf(m0, fmaxf(S[t8][0], S[t8][1]));
            m1 = fmaxf(m1, fmaxf(S[t8][2], S[t8][3]));
        }
        m0 = fmaxf(m0, __shfl_xor_sync(0xffffffffu, m0, 1));
        m0 = fmaxf(m0, __shfl_xor_sync(0xffffffffu, m0, 2));
        m1 = fmaxf(m1, __shfl_xor_sync(0xffffffffu, m1, 1));
        m1 = fmaxf(m1, __shfl_xor_sync(0xffffffffu, m1, 2));
        float l0 = 0.f, l1 = 0.f;
        #pragma unroll
        for (int t8 = 0; t8 < 8; t8++) {
            S[t8][0] = __expf(S[t8][0] - m0); l0 += S[t8][0];
            S[t8][1] = __expf(S[t8][1] - m0); l0 += S[t8][1];
            S[t8][2] = __expf(S[t8][2] - m1); l1 += S[t8][2];
            S[t8][3] = __expf(S[t8][3] - m1); l1 += S[t8][3];
        }
        l0 += __shfl_xor_sync(0xffffffffu, l0, 1);
        l0 += __shfl_xor_sync(0xffffffffu, l0, 2);
        l1 += __shfl_xor_sync(0xffffffffu, l1, 1);
        l1 += __shfl_xor_sync(0xffffffffu, l1, 2);
        float inv0 = __fdividef(1.0f, l0), inv1 = __fdividef(1.0f, l1);

        // O = (Ph + Pl) V, V single fp16
        #pragma unroll
        for (int nd = 0; nd < 4; nd++)
            #pragma unroll
            for (int e = 0; e < 4; e++) Oacc[ti][nd][e] = 0.f;
        #pragma unroll
        for (int kt = 0; kt < 4; kt++) {
            uint32_t ph[4], pl[4];
            pack_hilo_h(S[2 * kt][0], S[2 * kt][1], ph[0], pl[0]);
            pack_hilo_h(S[2 * kt][2], S[2 * kt][3], ph[1], pl[1]);
            pack_hilo_h(S[2 * kt + 1][0], S[2 * kt + 1][1], ph[2], pl[2]);
            pack_hilo_h(S[2 * kt + 1][2], S[2 * kt + 1][3], ph[3], pl[3]);
            #pragma unroll
            for (int db = 0; db < 2; db++) {
                int tok = kt * 16 + tokV;
                uint32_t ad = (uint32_t)tok * 256 +
                              (uint32_t)((((h * 4 + db * 2 + duV)) ^ (tok & 15)) << 4);
                uint32_t Vh[4];
                ldm4t(Vh, smb + OFF_VH + ad);
                mma_h(Oacc[ti][2 * db], ph, Vh[0], Vh[1]);
                mma_h(Oacc[ti][2 * db], pl, Vh[0], Vh[1]);
                mma_h(Oacc[ti][2 * db + 1], ph, Vh[2], Vh[3]);
                mma_h(Oacc[ti][2 * db + 1], pl, Vh[2], Vh[3]);
            }
        }
        #pragma unroll
        for (int nd = 0; nd < 4; nd++) {
            Oacc[ti][nd][0] *= inv0; Oacc[ti][nd][1] *= inv0;
            Oacc[ti][nd][2] *= inv1; Oacc[ti][nd][3] *= inv1;
        }
    }
    __syncthreads();   // all Q/K/V reads done; overwrite T0 with O (fp16 hi/lo)

    #pragma unroll
    for (int ti = 0; ti < 2; ti++) {
        const int t = wrp + ti * 8;
        const int h = t >> 2, mt = t & 3;
        #pragma unroll
        for (int nd = 0; nd < 4; nd++) {
            int col = h * 32 + nd * 8 + (lane & 3) * 2;
            int row = mt * 16 + (lane >> 2);
            uint32_t hiu, lou;
            pack_hilo_h(Oacc[ti][nd][0], Oacc[ti][nd][1], hiu, lou);
            uint32_t ad = tadr(row, col * 2);
            *(uint32_t*)(smc + OFF_T0H + ad) = hiu;
            *(uint32_t*)(smc + OFF_T0L + ad) = lou;
            pack_hilo_h(Oacc[ti][nd][2], Oacc[ti][nd][3], hiu, lou);
            ad = tadr(row + 8, col * 2);
            *(uint32_t*)(smc + OFF_T0H + ad) = hiu;
            *(uint32_t*)(smc + OFF_T0L + ad) = lou;
        }
    }
    __syncthreads();

    // ---- Phase 4: proj fp16 MMA, one-sided split (O hi+lo). Y fp32 -> OFF_Y ----
    {
        const int n0 = wrp * 16;
        float D[2][4][4];
        #pragma unroll
        for (int j = 0; j < 2; j++)
            #pragma unroll
            for (int mt = 0; mt < 4; mt++)
                #pragma unroll
                for (int e = 0; e < 4; e++) D[j][mt][e] = 0.f;

        #pragma unroll 1
        for (int s = 0; s < 8; s++) {
            uint32_t uoff = (uint32_t)(((s * 2 + h16) ^ rl) << 4);
            uint32_t Ah[4][4], Al[4][4];
            #pragma unroll
            for (int mt = 0; mt < 4; mt++) {
                ldm4(Ah[mt], smb + OFF_T0H + rl * 256 + mt * 4096 + uoff);
                ldm4(Al[mt], smb + OFF_T0L + rl * 256 + mt * 4096 + uoff);
            }
            #pragma unroll
            for (int j = 0; j < 2; j++) {
                uint2 bb = __ldg(&Bpk_g[((48 + wrp * 2 + j) * 8 + s) * 32 + lane]);
                #pragma unroll
                for (int mt = 0; mt < 4; mt++) {
                    mma_h(D[j][mt], Ah[mt], bb.x, bb.y);
                    mma_h(D[j][mt], Al[mt], bb.x, bb.y);
                }
            }
        }
        #pragma unroll
        for (int j = 0; j < 2; j++) {
            int c = n0 + j * 8 + (lane & 3) * 2;
            float2 bb = *(const float2*)(proj_b + c);
            #pragma unroll
            for (int mt = 0; mt < 4; mt++) {
                int row = mt * 16 + (lane >> 2);
                float2 o0, o1;
                o0.x = D[j][mt][0] + bb.x;
                o0.y = D[j][mt][1] + bb.y;
                o1.x = D[j][mt][2] + bb.x;
                o1.y = D[j][mt][3] + bb.y;
                *(float2*)(Yf + row * 132 + c)       = o0;
                *(float2*)(Yf + (row + 8) * 132 + c) = o1;
            }
        }
    }
    __syncthreads();

    // ---- Phase 5: reverse-roll scatter ----
    float* ob = out + base;
    #pragma unroll
    for (int i = tid; i < 2048; i += 256) {
        int cq = i >> 6, s = i & 63;
        float4 y = *(const float4*)(Yf + s * 132 + cq * 4);
        int sh = ((hn << 3) + (s >> 3) - 4) & 63;
        int sw = ((wn << 3) + (s & 7) - 4) & 63;
        float* po = ob + (cq * 4) * 102400 + sh * 64 + sw;
        po[0]      = y.x;
        po[102400] = y.y;
        po[204800] = y.z;
        po[307200] = y.w;
    }
}

extern "C" void kernel_launch(void* const* d_in, const int* in_sizes, int n_in,
                              void* d_out, int out_size) {
    (void)in_sizes; (void)n_in; (void)out_size;
    prep_w_kernel<<<64, 256>>>((const float*)d_in[1], (const float*)d_in[3]);
    cudaFuncSetAttribute(wattn_kernel, cudaFuncAttributeMaxDynamicSharedMemorySize, SMEM_BYTES);
    wattn_kernel<<<3200, 256, SMEM_BYTES>>>(
        (const float*)d_in[0], (const float*)d_in[2], (const float*)d_in[4],
        (const float*)d_in[5], (float*)d_out);
}

// round 16
// speedup vs baseline: 4.3740x; 1.2573x over previous
#include <cuda_runtime.h>
#include <cuda_bf16.h>
#include <cuda_fp16.h>
#include <cstdint>

typedef unsigned long long ull;
#define SC_Q 0.17677669529663687f

// ---- smem byte offsets (~86.5KB -> 2 CTAs/SM, bigger L1 carveout) ----
#define OFF_T0H 0          // X -> Q -> O  fp16 [64][256B] swizzled
#define OFF_KH  16384      // K fp16
#define OFF_VH  32768      // V fp16
#define OFF_Y   49152      // f32 [64][132] final Y
#define OFF_BT  82944      // rpb 900 f32
#define SMEM_BYTES 86544

__device__ __forceinline__ uint32_t smem_u32(const void* p) {
    uint32_t a;
    asm("{ .reg .u64 t; cvta.to.shared.u64 t, %1; cvt.u32.u64 %0, t; }" : "=r"(a) : "l"(p));
    return a;
}
// fp16 MMA
__device__ __forceinline__ void mma_h(float (&d)[4], const uint32_t (&a)[4], uint32_t b0, uint32_t b1) {
    asm volatile(
        "mma.sync.aligned.m16n8k16.row.col.f32.f16.f16.f32 "
        "{%0,%1,%2,%3}, {%4,%5,%6,%7}, {%8,%9}, {%0,%1,%2,%3};"
        : "+f"(d[0]), "+f"(d[1]), "+f"(d[2]), "+f"(d[3])
        : "r"(a[0]), "r"(a[1]), "r"(a[2]), "r"(a[3]), "r"(b0), "r"(b1));
}
__device__ __forceinline__ void ldm4(uint32_t (&a)[4], uint32_t addr) {
    asm volatile("ldmatrix.sync.aligned.m8n8.x4.shared.b16 {%0,%1,%2,%3}, [%4];"
                 : "=r"(a[0]), "=r"(a[1]), "=r"(a[2]), "=r"(a[3]) : "r"(addr));
}
__device__ __forceinline__ void ldm4t(uint32_t (&a)[4], uint32_t addr) {
    asm volatile("ldmatrix.sync.aligned.m8n8.x4.trans.shared.b16 {%0,%1,%2,%3}, [%4];"
                 : "=r"(a[0]), "=r"(a[1]), "=r"(a[2]), "=r"(a[3]) : "r"(addr));
}
__device__ __forceinline__ uint32_t h2u(__half2 h) {
    uint32_t u; memcpy(&u, &h, 4); return u;
}
// fp16 single pack
__device__ __forceinline__ uint32_t pack_h(float v0, float v1) {
    __half2 h2;
    h2.x = __float2half_rn(v0); h2.y = __float2half_rn(v1);
    return h2u(h2);
}
// tile address: row (0..63), byte-col cb (0..255); 16B-unit XOR swizzle
__device__ __forceinline__ uint32_t tadr(int row, int cb) {
    return (uint32_t)row * 256u + (uint32_t)((((cb >> 4) ^ (row & 15)) << 4) + (cb & 15));
}

// Packed fp16 B fragments: [n8 0..63][s 0..7][lane] = {b0,b1}; n8<48 qkv rows, else proj rows
__device__ __align__(16) uint2 Bpk_g[64 * 8 * 32];

__global__ void __launch_bounds__(256)
prep_w_kernel(const float* __restrict__ qkv_w, const float* __restrict__ proj_w) {
    int i = blockIdx.x * 256 + threadIdx.x;      // 16384 entries
    int n8 = i >> 8, s = (i >> 5) & 7, lane = i & 31;
    int n = n8 * 8 + (lane >> 2);
    int kb = s * 16 + (lane & 3) * 2;
    const float* src = (n < 384) ? (qkv_w + n * 128) : (proj_w + (n - 384) * 128);
    uint2 o;
    o.x = pack_h(src[kb], src[kb + 1]);
    o.y = pack_h(src[kb + 8], src[kb + 9]);
    Bpk_g[i] = o;
}

__global__ void __launch_bounds__(256, 2)
wattn_kernel(const float* __restrict__ x, const float* __restrict__ qkv_b,
             const float* __restrict__ proj_b, const float* __restrict__ rpb,
             float* __restrict__ out)
{
    extern __shared__ char smc[];
    float* Bt = (float*)(smc + OFF_BT);
    float* Yf = (float*)(smc + OFF_Y);

    const int tid = threadIdx.x;
    const int wrp = tid >> 5, lane = tid & 31;
    const uint32_t smb = smem_u32(smc);

    int wid = blockIdx.x;
    const int wn = wid & 7;  wid >>= 3;
    const int hn = wid & 7;  wid >>= 3;
    const int v  = wid % 5;  wid /= 5;
    const int u  = wid % 5;
    const int b  = wid / 5;
    const int base = (((b << 7) * 5 + u) * 5 + v) * 4096;
    const float* xb = x + base;

    // ---- Phase 1: roll+gather X -> swizzled fp16 T0H tile; rpb -> Bt ----
    {
        const int ml = (lane >> 2) & 7, cl = lane & 3;
        const int gm = wrp * 8 + ml;
        const int gsh = ((hn << 3) + (gm >> 3) - 4) & 63;
        const int gsw = ((wn << 3) + (gm & 7) - 4) & 63;
        const float* gp = xb + gsh * 64 + gsw;
        #pragma unroll
        for (int it = 0; it < 16; it++) {
            int cp = it * 4 + cl;
            float v0 = __ldg(gp + (2 * cp) * 102400);
            float v1 = __ldg(gp + (2 * cp + 1) * 102400);
            *(uint32_t*)(smc + OFF_T0H + tadr(gm, cp * 4)) = pack_h(v0, v1);
        }
    }
    for (int i = tid; i < 900; i += 256) Bt[i] = rpb[i];
    __syncthreads();

    // ldmatrix lane geometry (verified)
    const int rl  = ((lane >> 3) & 1) * 8 + (lane & 7);
    const int h16 = (lane >> 4) & 1;
    const int tokB = (lane & 7) + ((lane >> 4) << 3);
    const int kuB  = (lane >> 3) & 1;
    const int tokV = (lane & 7) + (((lane >> 3) & 1) << 3);
    const int duV  = (lane >> 4) & 1;

    // ---- Phase 2: QKV fp16 MMA (single precision both sides) ----
    {
        const int n0 = wrp * 48;
        float D[6][4][4];
        #pragma unroll
        for (int j = 0; j < 6; j++)
            #pragma unroll
            for (int mt = 0; mt < 4; mt++)
                #pragma unroll
                for (int e = 0; e < 4; e++) D[j][mt][e] = 0.f;

        #pragma unroll 1
        for (int s = 0; s < 8; s++) {
            uint32_t uoff = (uint32_t)(((s * 2 + h16) ^ rl) << 4);
            uint32_t A[4][4];
            #pragma unroll
            for (int mt = 0; mt < 4; mt++) ldm4(A[mt], smb + OFF_T0H + rl * 256 + mt * 4096 + uoff);
            #pragma unroll
            for (int j = 0; j < 6; j++) {
                uint2 bb = __ldg(&Bpk_g[((wrp * 6 + j) * 8 + s) * 32 + lane]);
                #pragma unroll
                for (int mt = 0; mt < 4; mt++) mma_h(D[j][mt], A[mt], bb.x, bb.y);
            }
        }
        __syncthreads();   // all A-reads of T0 done; safe to overwrite T0 with Q

        // epilogue: remap head-interleaved cols; Q (scaled)->T0H, K->KH, V->VH (all single fp16)
        #pragma unroll
        for (int j = 0; j < 6; j++) {
            int c  = n0 + j * 8 + (lane & 3) * 2;
            int hh = c / 96, r = c - hh * 96;
            int seg = r >> 5, col = (hh << 5) + (r & 31);
            int tb = (seg == 0) ? OFF_T0H : (seg == 1) ? OFF_KH : OFF_VH;
            float sc = (seg == 0) ? SC_Q : 1.0f;
            float b0 = __ldg(qkv_b + c), b1 = __ldg(qkv_b + c + 1);
            #pragma unroll
            for (int mt = 0; mt < 4; mt++) {
                int row = mt * 16 + (lane >> 2);
                *(uint32_t*)(smc + tb + tadr(row, col * 2)) =
                    pack_h((D[j][mt][0] + b0) * sc, (D[j][mt][1] + b1) * sc);
                *(uint32_t*)(smc + tb + tadr(row + 8, col * 2)) =
                    pack_h((D[j][mt][2] + b0) * sc, (D[j][mt][3] + b1) * sc);
            }
        }
    }
    __syncthreads();

    // ---- Phase 3: tensor attention (full fp16). 16 tasks; warp -> w, w+8 ----
    float Oacc[2][4][4];
    #pragma unroll 1
    for (int ti = 0; ti < 2; ti++) {
        const int t = wrp + ti * 8;
        const int h = t >> 2, mt = t & 3;

        float S[8][4];
        #pragma unroll
        for (int t8 = 0; t8 < 8; t8++)
            #pragma unroll
            for (int e = 0; e < 4; e++) S[t8][e] = 0.f;

        uint32_t Qh[2][4];
        #pragma unroll
        for (int ks = 0; ks < 2; ks++) {
            uint32_t uo = (uint32_t)(((h * 4 + ks * 2 + h16) ^ rl) << 4);
            ldm4(Qh[ks], smb + OFF_T0H + (mt * 16 + rl) * 256 + uo);
        }
        // S = Q K^T (single fp16)
        #pragma unroll
        for (int ks = 0; ks < 2; ks++) {
            #pragma unroll
            for (int nb = 0; nb < 4; nb++) {
                int tok = nb * 16 + tokB;
                uint32_t ad = (uint32_t)tok * 256 + (uint32_t)(((h * 4 + ks * 2 + kuB) ^ (tok & 15)) << 4);
                uint32_t Bh[4];
                ldm4(Bh, smb + OFF_KH + ad);
                mma_h(S[2 * nb],     Qh[ks], Bh[0], Bh[1]);
                mma_h(S[2 * nb + 1], Qh[ks], Bh[2], Bh[3]);
            }
        }
        // + relative position bias
        const int r0g = mt * 16 + (lane >> 2);
        const int cb2 = (lane & 3) * 2;
        #pragma unroll
        for (int t8 = 0; t8 < 8; t8++) {
            #pragma unroll
            for (int e = 0; e < 4; e++) {
                int row = r0g + ((e >> 1) << 3);
                int col = t8 * 8 + cb2 + (e & 1);
                int ridx = ((row >> 3) - (col >> 3) + 7) * 15 + ((row & 7) - (col & 7) + 7);
                S[t8][e] += Bt[ridx * 4 + h];
            }
        }
        // softmax over fragment rows (quad-shfl reduce)
        float m0 = S[0][0], m1 = S[0][2];
        #pragma unroll
        for (int t8 = 0; t8 < 8; t8++) {
            m0 = fmaxf(m0, fmaxf(S[t8][0], S[t8][1]));
            m1 = fmaxf(m1, fmaxf(S[t8][2], S[t8][3]));
        }
        m0 = fmaxf(m0, __shfl_xor_sync(0xffffffffu, m0, 1));
        m0 = fmaxf(m0, __shfl_xor_sync(0xffffffffu, m0, 2));
        m1 = fmaxf(m1, __shfl_xor_sync(0xffffffffu, m1, 1));
        m1 = fmaxf(m1, __shfl_xor_sync(0xffffffffu, m1, 2));
        float l0 = 0.f, l1 = 0.f;
        #pragma unroll
        for (int t8 = 0; t8 < 8; t8++) {
            S[t8][0] = __expf(S[t8][0] - m0); l0 += S[t8][0];
            S[t8][1] = __expf(S[t8][1] - m0); l0 += S[t8][1];
            S[t8][2] = __expf(S[t8][2] - m1); l1 += S[t8][2];
            S[t8][3] = __expf(S[t8][3] - m1); l1 += S[t8][3];
        }
        l0 += __shfl_xor_sync(0xffffffffu, l0, 1);
        l0 += __shfl_xor_sync(0xffffffffu, l0, 2);
        l1 += __shfl_xor_sync(0xffffffffu, l1, 1);
        l1 += __shfl_xor_sync(0xffffffffu, l1, 2);
        float inv0 = __fdividef(1.0f, l0), inv1 = __fdividef(1.0f, l1);

        // O = P V (single fp16 both sides)
        #pragma unroll
        for (int nd = 0; nd < 4; nd++)
            #pragma unroll
            for (int e = 0; e < 4; e++) Oacc[ti][nd][e] = 0.f;
        #pragma unroll
        for (int kt = 0; kt < 4; kt++) {
            uint32_t ph[4];
            ph[0] = pack_h(S[2 * kt][0],     S[2 * kt][1]);
            ph[1] = pack_h(S[2 * kt][2],     S[2 * kt][3]);
            ph[2] = pack_h(S[2 * kt + 1][0], S[2 * kt + 1][1]);
            ph[3] = pack_h(S[2 * kt + 1][2], S[2 * kt + 1][3]);
            #pragma unroll
            for (int db = 0; db < 2; db++) {
                int tok = kt * 16 + tokV;
                uint32_t ad = (uint32_t)tok * 256 +
                              (uint32_t)((((h * 4 + db * 2 + duV)) ^ (tok & 15)) << 4);
                uint32_t Vh[4];
                ldm4t(Vh, smb + OFF_VH + ad);
                mma_h(Oacc[ti][2 * db],     ph, Vh[0], Vh[1]);
                mma_h(Oacc[ti][2 * db + 1], ph, Vh[2], Vh[3]);
            }
        }
        #pragma unroll
        for (int nd = 0; nd < 4; nd++) {
            Oacc[ti][nd][0] *= inv0; Oacc[ti][nd][1] *= inv0;
            Oacc[ti][nd][2] *= inv1; Oacc[ti][nd][3] *= inv1;
        }
    }
    __syncthreads();   // all Q/K/V reads done; overwrite T0 with O (single fp16)

    #pragma unroll
    for (int ti = 0; ti < 2; ti++) {
        const int t = wrp + ti * 8;
        const int h = t >> 2, mt = t & 3;
        #pragma unroll
        for (int nd = 0; nd < 4; nd++) {
            int col = h * 32 + nd * 8 + (lane & 3) * 2;
            int row = mt * 16 + (lane >> 2);
            *(uint32_t*)(smc + OFF_T0H + tadr(row, col * 2)) =
                pack_h(Oacc[ti][nd][0], Oacc[ti][nd][1]);
            *(uint32_t*)(smc + OFF_T0H + tadr(row + 8, col * 2)) =
                pack_h(Oacc[ti][nd][2], Oacc[ti][nd][3]);
        }
    }
    __syncthreads();

    // ---- Phase 4: proj fp16 MMA (single precision). Y fp32 -> OFF_Y ----
    {
        const int n0 = wrp * 16;
        float D[2][4][4];
        #pragma unroll
        for (int j = 0; j < 2; j++)
            #pragma unroll
            for (int mt = 0; mt < 4; mt++)
                #pragma unroll
                for (int e = 0; e < 4; e++) D[j][mt][e] = 0.f;

        #pragma unroll 1
        for (int s = 0; s < 8; s++) {
            uint32_t uoff = (uint32_t)(((s * 2 + h16) ^ rl) << 4);
            uint32_t Ah[4][4];
            #pragma unroll
            for (int mt = 0; mt < 4; mt++)
                ldm4(Ah[mt], smb + OFF_T0H + rl * 256 + mt * 4096 + uoff);
            #pragma unroll
            for (int j = 0; j < 2; j++) {
                uint2 bb = __ldg(&Bpk_g[((48 + wrp * 2 + j) * 8 + s) * 32 + lane]);
                #pragma unroll
                for (int mt = 0; mt < 4; mt++) mma_h(D[j][mt], Ah[mt], bb.x, bb.y);
            }
        }
        #pragma unroll
        for (int j = 0; j < 2; j++) {
            int c = n0 + j * 8 + (lane & 3) * 2;
            float2 bb = *(const float2*)(proj_b + c);
            #pragma unroll
            for (int mt = 0; mt < 4; mt++) {
                int row = mt * 16 + (lane >> 2);
                float2 o0, o1;
                o0.x = D[j][mt][0] + bb.x;
                o0.y = D[j][mt][1] + bb.y;
                o1.x = D[j][mt][2] + bb.x;
                o1.y = D[j][mt][3] + bb.y;
                *(float2*)(Yf + row * 132 + c)       = o0;
                *(float2*)(Yf + (row + 8) * 132 + c) = o1;
            }
        }
    }
    __syncthreads();

    // ---- Phase 5: reverse-roll scatter ----
    float* ob = out + base;
    #pragma unroll
    for (int i = tid; i < 2048; i += 256) {
        int cq = i >> 6, s = i & 63;
        float4 y = *(const float4*)(Yf + s * 132 + cq * 4);
        int sh = ((hn << 3) + (s >> 3) - 4) & 63;
        int sw = ((wn << 3) + (s & 7) - 4) & 63;
        float* po = ob + (cq * 4) * 102400 + sh * 64 + sw;
        po[0]      = y.x;
        po[102400] = y.y;
        po[204800] = y.z;
        po[307200] = y.w;
    }
}

extern "C" void kernel_launch(void* const* d_in, const int* in_sizes, int n_in,
                              void* d_out, int out_size) {
    (void)in_sizes; (void)n_in; (void)out_size;
    prep_w_kernel<<<64, 256>>>((const float*)d_in[1], (const float*)d_in[3]);
    cudaFuncSetAttribute(wattn_kernel, cudaFuncAttributeMaxDynamicSharedMemorySize, SMEM_BYTES);
    wattn_kernel<<<3200, 256, SMEM_BYTES>>>(
        (const float*)d_in[0], (const float*)d_in[2], (const float*)d_in[4],
        (const float*)d_in[5], (float*)d_out);
}

// round 17
// speedup vs baseline: 4.6808x; 1.0702x over previous
#include <cuda_runtime.h>
#include <cuda_fp16.h>
#include <cstdint>

#define SC_Q 0.17677669529663687f

// ---- smem byte offsets (~67.5KB -> 3 CTAs/SM) ----
#define OFF_T0 0           // X (fp16 tiles) -> O (fp16 tiles)
#define OFF_KH 16384       // K fp16
#define OFF_VH 32768       // V fp16
#define OFF_OT 49152       // Q fp16 tiles
#define OFF_BT 65536       // rpb 900 f32
#define OFF_Y  16384       // f32 [64][132] final Y (aliases dead KH+VH+OT head)
#define SMEM_BYTES 69136

__device__ __forceinline__ uint32_t smem_u32(const void* p) {
    uint32_t a;
    asm("{ .reg .u64 t; cvta.to.shared.u64 t, %1; cvt.u32.u64 %0, t; }" : "=r"(a) : "l"(p));
    return a;
}
__device__ __forceinline__ void mma_h(float (&d)[4], const uint32_t (&a)[4], uint32_t b0, uint32_t b1) {
    asm volatile(
        "mma.sync.aligned.m16n8k16.row.col.f32.f16.f16.f32 "
        "{%0,%1,%2,%3}, {%4,%5,%6,%7}, {%8,%9}, {%0,%1,%2,%3};"
        : "+f"(d[0]), "+f"(d[1]), "+f"(d[2]), "+f"(d[3])
        : "r"(a[0]), "r"(a[1]), "r"(a[2]), "r"(a[3]), "r"(b0), "r"(b1));
}
__device__ __forceinline__ void ldm4(uint32_t (&a)[4], uint32_t addr) {
    asm volatile("ldmatrix.sync.aligned.m8n8.x4.shared.b16 {%0,%1,%2,%3}, [%4];"
                 : "=r"(a[0]), "=r"(a[1]), "=r"(a[2]), "=r"(a[3]) : "r"(addr));
}
__device__ __forceinline__ void ldm4t(uint32_t (&a)[4], uint32_t addr) {
    asm volatile("ldmatrix.sync.aligned.m8n8.x4.trans.shared.b16 {%0,%1,%2,%3}, [%4];"
                 : "=r"(a[0]), "=r"(a[1]), "=r"(a[2]), "=r"(a[3]) : "r"(addr));
}
__device__ __forceinline__ uint32_t h2u(__half2 h) {
    uint32_t u; memcpy(&u, &h, 4); return u;
}
__device__ __forceinline__ uint32_t pack_h(float v0, float v1) {
    __half2 h2;
    h2.x = __float2half_rn(v0); h2.y = __float2half_rn(v1);
    return h2u(h2);
}
// tile address: row (0..63), byte-col cb (0..255); 16B-unit XOR swizzle
__device__ __forceinline__ uint32_t tadr(int row, int cb) {
    return (uint32_t)row * 256u + (uint32_t)((((cb >> 4) ^ (row & 15)) << 4) + (cb & 15));
}

// Packed fp16 B fragments, paired k-steps: [n8 0..63][sp 0..3][lane] =
// {s=2sp:(b0,b1), s=2sp+1:(b0,b1)}; n8<48 qkv rows, else proj rows
__device__ __align__(16) uint4 Bpk_g[64 * 4 * 32];

__global__ void __launch_bounds__(256)
prep_w_kernel(const float* __restrict__ qkv_w, const float* __restrict__ proj_w) {
    int i = blockIdx.x * 256 + threadIdx.x;      // 8192 entries
    int n8 = i >> 7, sp = (i >> 5) & 3, lane = i & 31;
    int n = n8 * 8 + (lane >> 2);
    int kb0 = sp * 32 + (lane & 3) * 2;
    const float* src = (n < 384) ? (qkv_w + n * 128) : (proj_w + (n - 384) * 128);
    uint4 o;
    o.x = pack_h(src[kb0],      src[kb0 + 1]);
    o.y = pack_h(src[kb0 + 8],  src[kb0 + 9]);
    o.z = pack_h(src[kb0 + 16], src[kb0 + 17]);
    o.w = pack_h(src[kb0 + 24], src[kb0 + 25]);
    Bpk_g[i] = o;
}

__global__ void __launch_bounds__(256, 3)
wattn_kernel(const float* __restrict__ x, const float* __restrict__ qkv_b,
             const float* __restrict__ proj_b, const float* __restrict__ rpb,
             float* __restrict__ out)
{
    extern __shared__ char smc[];
    float* Bt = (float*)(smc + OFF_BT);
    float* Yf = (float*)(smc + OFF_Y);

    const int tid = threadIdx.x;
    const int wrp = tid >> 5, lane = tid & 31;
    const uint32_t smb = smem_u32(smc);

    int wid = blockIdx.x;
    const int wn = wid & 7;  wid >>= 3;
    const int hn = wid & 7;  wid >>= 3;
    const int v  = wid % 5;  wid /= 5;
    const int u  = wid % 5;
    const int b  = wid / 5;
    const int base = (((b << 7) * 5 + u) * 5 + v) * 4096;
    const float* xb = x + base;

    // ---- Phase 1: roll+gather X -> swizzled fp16 T0 tile; rpb -> Bt ----
    {
        const int ml = (lane >> 2) & 7, cl = lane & 3;
        const int gm = wrp * 8 + ml;
        const int gsh = ((hn << 3) + (gm >> 3) - 4) & 63;
        const int gsw = ((wn << 3) + (gm & 7) - 4) & 63;
        const float* gp = xb + gsh * 64 + gsw;
        #pragma unroll
        for (int it = 0; it < 16; it++) {
            int cp = it * 4 + cl;
            float v0 = __ldg(gp + (2 * cp) * 102400);
            float v1 = __ldg(gp + (2 * cp + 1) * 102400);
            *(uint32_t*)(smc + OFF_T0 + tadr(gm, cp * 4)) = pack_h(v0, v1);
        }
    }
    for (int i = tid; i < 900; i += 256) Bt[i] = rpb[i];
    __syncthreads();

    // ldmatrix lane geometry (verified)
    const int rl  = ((lane >> 3) & 1) * 8 + (lane & 7);
    const int h16 = (lane >> 4) & 1;
    const int tokB = (lane & 7) + ((lane >> 4) << 3);
    const int kuB  = (lane >> 3) & 1;
    const int tokV = (lane & 7) + (((lane >> 3) & 1) << 3);
    const int duV  = (lane >> 4) & 1;

    // ---- Phase 2: QKV fp16 MMA, two half-passes of 24 cols (D=48 regs) ----
    #pragma unroll 1
    for (int p = 0; p < 2; p++) {
        float D[3][4][4];
        #pragma unroll
        for (int j = 0; j < 3; j++)
            #pragma unroll
            for (int mt = 0; mt < 4; mt++)
                #pragma unroll
                for (int e = 0; e < 4; e++) D[j][mt][e] = 0.f;

        const int nb8 = wrp * 6 + p * 3;
        #pragma unroll 1
        for (int sp = 0; sp < 4; sp++) {
            uint4 bb[3];
            #pragma unroll
            for (int j = 0; j < 3; j++)
                bb[j] = __ldg(&Bpk_g[((nb8 + j) * 4 + sp) * 32 + lane]);
            #pragma unroll
            for (int sh = 0; sh < 2; sh++) {
                int s = sp * 2 + sh;
                uint32_t uoff = (uint32_t)(((s * 2 + h16) ^ rl) << 4);
                uint32_t A[4][4];
                #pragma unroll
                for (int mt = 0; mt < 4; mt++)
                    ldm4(A[mt], smb + OFF_T0 + rl * 256 + mt * 4096 + uoff);
                #pragma unroll
                for (int j = 0; j < 3; j++) {
                    uint32_t b0 = sh ? bb[j].z : bb[j].x;
                    uint32_t b1 = sh ? bb[j].w : bb[j].y;
                    #pragma unroll
                    for (int mt = 0; mt < 4; mt++) mma_h(D[j][mt], A[mt], b0, b1);
                }
            }
        }
        // epilogue: remap head-interleaved cols; Q (scaled)->OT, K->KH, V->VH
        #pragma unroll
        for (int j = 0; j < 3; j++) {
            int c  = wrp * 48 + p * 24 + j * 8 + (lane & 3) * 2;
            int hh = c / 96, r = c - hh * 96;
            int seg = r >> 5, col = (hh << 5) + (r & 31);
            int tb = (seg == 0) ? OFF_OT : (seg == 1) ? OFF_KH : OFF_VH;
            float sc = (seg == 0) ? SC_Q : 1.0f;
            float b0 = __ldg(qkv_b + c), b1 = __ldg(qkv_b + c + 1);
            #pragma unroll
            for (int mt = 0; mt < 4; mt++) {
                int row = mt * 16 + (lane >> 2);
                *(uint32_t*)(smc + tb + tadr(row, col * 2)) =
                    pack_h((D[j][mt][0] + b0) * sc, (D[j][mt][1] + b1) * sc);
                *(uint32_t*)(smc + tb + tadr(row + 8, col * 2)) =
                    pack_h((D[j][mt][2] + b0) * sc, (D[j][mt][3] + b1) * sc);
            }
        }
    }
    __syncthreads();

    // ---- Phase 3: tensor attention (fp16). 16 tasks; warp -> w, w+8. O -> T0 ----
    #pragma unroll 1
    for (int ti = 0; ti < 2; ti++) {
        const int t = wrp + ti * 8;
        const int h = t >> 2, mt = t & 3;

        float S[8][4];
        #pragma unroll
        for (int t8 = 0; t8 < 8; t8++)
            #pragma unroll
            for (int e = 0; e < 4; e++) S[t8][e] = 0.f;

        uint32_t Qh[2][4];
        #pragma unroll
        for (int ks = 0; ks < 2; ks++) {
            uint32_t uo = (uint32_t)(((h * 4 + ks * 2 + h16) ^ rl) << 4);
            ldm4(Qh[ks], smb + OFF_OT + (mt * 16 + rl) * 256 + uo);
        }
        // S = Q K^T
        #pragma unroll
        for (int ks = 0; ks < 2; ks++) {
            #pragma unroll
            for (int nb = 0; nb < 4; nb++) {
                int tok = nb * 16 + tokB;
                uint32_t ad = (uint32_t)tok * 256 + (uint32_t)(((h * 4 + ks * 2 + kuB) ^ (tok & 15)) << 4);
                uint32_t Bh[4];
                ldm4(Bh, smb + OFF_KH + ad);
                mma_h(S[2 * nb],     Qh[ks], Bh[0], Bh[1]);
                mma_h(S[2 * nb + 1], Qh[ks], Bh[2], Bh[3]);
            }
        }
        // + relative position bias
        const int r0g = mt * 16 + (lane >> 2);
        const int cb2 = (lane & 3) * 2;
        #pragma unroll
        for (int t8 = 0; t8 < 8; t8++) {
            #pragma unroll
            for (int e = 0; e < 4; e++) {
                int row = r0g + ((e >> 1) << 3);
                int col = t8 * 8 + cb2 + (e & 1);
                int ridx = ((row >> 3) - (col >> 3) + 7) * 15 + ((row & 7) - (col & 7) + 7);
                S[t8][e] += Bt[ridx * 4 + h];
            }
        }
        // softmax (quad-shfl reduce)
        float m0 = S[0][0], m1 = S[0][2];
        #pragma unroll
        for (int t8 = 0; t8 < 8; t8++) {
            m0 = fmaxf(m0, fmaxf(S[t8][0], S[t8][1]));
            m1 = fmaxf(m1, fmaxf(S[t8][2], S[t8][3]));
        }
        m0 = fmaxf(m0, __shfl_xor_sync(0xffffffffu, m0, 1));
        m0 = fmaxf(m0, __shfl_xor_sync(0xffffffffu, m0, 2));
        m1 = fmaxf(m1, __shfl_xor_sync(0xffffffffu, m1, 1));
        m1 = fmaxf(m1, __shfl_xor_sync(0xffffffffu, m1, 2));
        float l0 = 0.f, l1 = 0.f;
        #pragma unroll
        for (int t8 = 0; t8 < 8; t8++) {
            S[t8][0] = __expf(S[t8][0] - m0); l0 += S[t8][0];
            S[t8][1] = __expf(S[t8][1] - m0); l0 += S[t8][1];
            S[t8][2] = __expf(S[t8][2] - m1); l1 += S[t8][2];
            S[t8][3] = __expf(S[t8][3] - m1); l1 += S[t8][3];
        }
        l0 += __shfl_xor_sync(0xffffffffu, l0, 1);
        l0 += __shfl_xor_sync(0xffffffffu, l0, 2);
        l1 += __shfl_xor_sync(0xffffffffu, l1, 1);
        l1 += __shfl_xor_sync(0xffffffffu, l1, 2);
        float inv0 = __fdividef(1.0f, l0), inv1 = __fdividef(1.0f, l1);

        // O = P V
        float Oacc[4][4];
        #pragma unroll
        for (int nd = 0; nd < 4; nd++)
            #pragma unroll
            for (int e = 0; e < 4; e++) Oacc[nd][e] = 0.f;
        #pragma unroll
        for (int kt = 0; kt < 4; kt++) {
            uint32_t ph[4];
            ph[0] = pack_h(S[2 * kt][0],     S[2 * kt][1]);
            ph[1] = pack_h(S[2 * kt][2],     S[2 * kt][3]);
            ph[2] = pack_h(S[2 * kt + 1][0], S[2 * kt + 1][1]);
            ph[3] = pack_h(S[2 * kt + 1][2], S[2 * kt + 1][3]);
            #pragma unroll
            for (int db = 0; db < 2; db++) {
                int tok = kt * 16 + tokV;
                uint32_t ad = (uint32_t)tok * 256 +
                              (uint32_t)((((h * 4 + db * 2 + duV)) ^ (tok & 15)) << 4);
                uint32_t Vh[4];
                ldm4t(Vh, smb + OFF_VH + ad);
                mma_h(Oacc[2 * db],     ph, Vh[0], Vh[1]);
                mma_h(Oacc[2 * db + 1], ph, Vh[2], Vh[3]);
            }
        }
        // store O for this task immediately (T0 = dead X region; no race)
        #pragma unroll
        for (int nd = 0; nd < 4; nd++) {
            int col = h * 32 + nd * 8 + (lane & 3) * 2;
            int row = mt * 16 + (lane >> 2);
            *(uint32_t*)(smc + OFF_T0 + tadr(row, col * 2)) =
                pack_h(Oacc[nd][0] * inv0, Oacc[nd][1] * inv0);
            *(uint32_t*)(smc + OFF_T0 + tadr(row + 8, col * 2)) =
                pack_h(Oacc[nd][2] * inv1, Oacc[nd][3] * inv1);
        }
    }
    __syncthreads();

    // ---- Phase 4: proj fp16 MMA (A = O in T0). Y fp32 -> alias over KH/VH/OT ----
    {
        const int n0 = wrp * 16;
        float D[2][4][4];
        #pragma unroll
        for (int j = 0; j < 2; j++)
            #pragma unroll
            for (int mt = 0; mt < 4; mt++)
                #pragma unroll
                for (int e = 0; e < 4; e++) D[j][mt][e] = 0.f;

        #pragma unroll 1
        for (int sp = 0; sp < 4; sp++) {
            uint4 bb[2];
            #pragma unroll
            for (int j = 0; j < 2; j++)
                bb[j] = __ldg(&Bpk_g[((48 + wrp * 2 + j) * 4 + sp) * 32 + lane]);
            #pragma unroll
            for (int sh = 0; sh < 2; sh++) {
                int s = sp * 2 + sh;
                uint32_t uoff = (uint32_t)(((s * 2 + h16) ^ rl) << 4);
                uint32_t A[4][4];
                #pragma unroll
                for (int mt = 0; mt < 4; mt++)
                    ldm4(A[mt], smb + OFF_T0 + rl * 256 + mt * 4096 + uoff);
                #pragma unroll
                for (int j = 0; j < 2; j++) {
                    uint32_t b0 = sh ? bb[j].z : bb[j].x;
                    uint32_t b1 = sh ? bb[j].w : bb[j].y;
                    #pragma unroll
                    for (int mt = 0; mt < 4; mt++) mma_h(D[j][mt], A[mt], b0, b1);
                }
            }
        }
        #pragma unroll
        for (int j = 0; j < 2; j++) {
            int c = n0 + j * 8 + (lane & 3) * 2;
            float2 bb = *(const float2*)(proj_b + c);
            #pragma unroll
            for (int mt = 0; mt < 4; mt++) {
                int row = mt * 16 + (lane >> 2);
                float2 o0, o1;
                o0.x = D[j][mt][0] + bb.x;
                o0.y = D[j][mt][1] + bb.y;
                o1.x = D[j][mt][2] + bb.x;
                o1.y = D[j][mt][3] + bb.y;
                *(float2*)(Yf + row * 132 + c)       = o0;
                *(float2*)(Yf + (row + 8) * 132 + c) = o1;
            }
        }
    }
    __syncthreads();

    // ---- Phase 5: reverse-roll scatter ----
    float* ob = out + base;
    #pragma unroll
    for (int i = tid; i < 2048; i += 256) {
        int cq = i >> 6, s = i & 63;
        float4 y = *(const float4*)(Yf + s * 132 + cq * 4);
        int sh = ((hn << 3) + (s >> 3) - 4) & 63;
        int sw = ((wn << 3) + (s & 7) - 4) & 63;
        float* po = ob + (cq * 4) * 102400 + sh * 64 + sw;
        po[0]      = y.x;
        po[102400] = y.y;
        po[204800] = y.z;
        po[307200] = y.w;
    }
}

extern "C" void kernel_launch(void* const* d_in, const int* in_sizes, int n_in,
                              void* d_out, int out_size) {
    (void)in_sizes; (void)n_in; (void)out_size;
    prep_w_kernel<<<32, 256>>>((const float*)d_in[1], (const float*)d_in[3]);
    cudaFuncSetAttribute(wattn_kernel, cudaFuncAttributeMaxDynamicSharedMemorySize, SMEM_BYTES);
    wattn_kernel<<<3200, 256, SMEM_BYTES>>>(
        (const float*)d_in[0], (const float*)d_in[2], (const float*)d_in[4],
        (const float*)d_in[5], (float*)d_out);
}